// round 8
// baseline (speedup 1.0000x reference)
#include <cuda_runtime.h>
#include <cstdint>

// CapsuleLayer: conv(stride2,3x3) via mma.sync tf32, 3x dynamic routing (batch-
// split for L2 residency of u_hat), fused final-route+transpose.
// x: [8,8,32,64,64] fp32   W: [512,32,3,3]   bias: [512]
// out: [8,8,64,32,32] (N,T1,Z1,H1,W1) fp32

#define DEVINL __device__ __forceinline__

DEVINL uint32_t smem_u32(const void* p) {
    uint32_t a;
    asm("{ .reg .u64 t; cvta.to.shared.u64 t, %1; cvt.u32.u64 %0, t; }" : "=r"(a) : "l"(p));
    return a;
}
DEVINL void cp16(uint32_t dst, const void* src) {
    asm volatile("cp.async.cg.shared.global [%0], [%1], 16;" ::"r"(dst), "l"(src) : "memory");
}

// ---------------------------------------------------------------------------
__device__ __align__(128) float g_xt[64 * 66 * 66 * 32];        // NHWC padded, tf32
__device__ __align__(128) float g_w2[9 * 512 * 32];             // [kpos][oc][ic], tf32
__device__ __align__(128) float g_u2[8 * 32 * 32 * 8 * 8 * 64]; // [n][h][w][t0][t1][z]
__device__ __align__(128) float g_b [8 * 8 * 32 * 32 * 8];      // [n][t0][h][w][t1]
__device__ __align__(128) float g_r [8 * 8 * 32 * 32 * 8];

// ---------------------------------------------------------------------------
// 1) x -> g_xt  (NCHW -> padded NHWC, tf32 rounding)
// ---------------------------------------------------------------------------
__global__ __launch_bounds__(256) void xt_kernel(const float* __restrict__ x) {
    __shared__ float s[64 * 33];
    const int b = blockIdx.y, h0 = blockIdx.x;
    const int t = threadIdx.x;
    const int lane = t & 31, icg = t >> 5;
    const float* xp = x + ((size_t)(b * 32) * 64 + h0) * 64;
#pragma unroll
    for (int i = 0; i < 4; i++) {
        int ic = icg + 8 * i;
        s[lane * 33 + ic]        = xp[(size_t)ic * 4096 + lane];
        s[(lane + 32) * 33 + ic] = xp[(size_t)ic * 4096 + lane + 32];
    }
    __syncthreads();
    uint32_t* dst = (uint32_t*)(g_xt + (((size_t)b * 66 + h0 + 1) * 66 + 1) * 32);
#pragma unroll
    for (int i = 0; i < 8; i++) {
        int idx = t + 256 * i;
        int w0 = idx >> 5, ic = idx & 31;
        uint32_t u;
        asm("cvt.rna.tf32.f32 %0, %1;" : "=r"(u) : "f"(s[w0 * 33 + ic]));
        dst[idx] = u;
    }
}

// ---------------------------------------------------------------------------
// 2) W -> g_w2 [kpos][oc][ic] tf32
// ---------------------------------------------------------------------------
__global__ void w2_kernel(const float* __restrict__ W) {
    int idx = blockIdx.x * 256 + threadIdx.x;   // oc*288 + ic*9 + kp
    if (idx >= 512 * 288) return;
    int oc = idx / 288, r = idx % 288, ic = r / 9, kp = r % 9;
    uint32_t u;
    asm("cvt.rna.tf32.f32 %0, %1;" : "=r"(u) : "f"(W[idx]));
    ((uint32_t*)g_w2)[((size_t)kp * 512 + oc) * 32 + ic] = u;
}

// ---------------------------------------------------------------------------
// 3) conv via mma.sync tf32 (R3 configuration, + batch-group offset b0)
// ---------------------------------------------------------------------------
#define TSTRIDE 36
#define TILE_F  (128 * TSTRIDE)

__global__ __launch_bounds__(256, 2) void conv_mma_kernel(const float* __restrict__ bias,
                                                          int b0) {
    extern __shared__ float dsm[];
    const uint32_t sbase = smem_u32(dsm);
    const uint32_t offA[2] = {0u, 2u * TILE_F * 4u};
    const uint32_t offB[2] = {TILE_F * 4u, 3u * TILE_F * 4u};

    const int tid = threadIdx.x;
    const int wid = tid >> 5, lane = tid & 31;
    const int gid = lane >> 2, tig = lane & 3;

    const int pt = blockIdx.x;          // pixel tile (4 output rows)
    const int m  = blockIdx.y;          // oc block of 128
    const int b  = blockIdx.z + b0;     // n*8 + t0
    const int h0 = pt * 4;

    const int m0 = (wid & 1) * 64;
    const int n0 = (wid >> 1) * 32;

    float acc[4][4][4];
#pragma unroll
    for (int mi = 0; mi < 4; mi++)
#pragma unroll
        for (int ni = 0; ni < 4; ni++)
#pragma unroll
            for (int j = 0; j < 4; j++) acc[mi][ni][j] = 0.f;

    auto issue = [&](int s, int buf) {
        const int kh = s / 3, kw = s % 3;
        const float4* Asrc = (const float4*)g_w2 + ((size_t)s * 512 + m * 128) * 8;
        const int ihb = 2 * h0 + kh;
#pragma unroll
        for (int i = 0; i < 4; i++) {
            int c = tid + 256 * i;
            int o = c >> 3, q = c & 7;
            cp16(sbase + offA[buf] + (o * TSTRIDE + q * 4) * 4, Asrc + c);
            int hl = o >> 5, wl = o & 31;
            const float4* src =
                (const float4*)g_xt + (((size_t)b * 66 + ihb + 2 * hl) * 66 + 2 * wl + kw) * 8 + q;
            cp16(sbase + offB[buf] + (o * TSTRIDE + q * 4) * 4, src);
        }
        asm volatile("cp.async.commit_group;");
    };

    issue(0, 0);

    for (int s = 0; s < 9; s++) {
        if (s < 8) {
            issue(s + 1, (s + 1) & 1);
            asm volatile("cp.async.wait_group 1;" ::: "memory");
        } else {
            asm volatile("cp.async.wait_group 0;" ::: "memory");
        }
        __syncthreads();

        const uint32_t* sA = (const uint32_t*)dsm + offA[s & 1] / 4;
        const uint32_t* sB = (const uint32_t*)dsm + offB[s & 1] / 4;

#pragma unroll
        for (int kk = 0; kk < 4; kk++) {
            const int kc = kk * 8 + tig;
            uint32_t a[4][4];
#pragma unroll
            for (int mi = 0; mi < 4; mi++) {
                int r = m0 + mi * 16 + gid;
                a[mi][0] = sA[r * TSTRIDE + kc];
                a[mi][1] = sA[(r + 8) * TSTRIDE + kc];
                a[mi][2] = sA[r * TSTRIDE + kc + 4];
                a[mi][3] = sA[(r + 8) * TSTRIDE + kc + 4];
            }
            uint32_t bf[4][2];
#pragma unroll
            for (int ni = 0; ni < 4; ni++) {
                int cn = n0 + ni * 8 + gid;
                bf[ni][0] = sB[cn * TSTRIDE + kc];
                bf[ni][1] = sB[cn * TSTRIDE + kc + 4];
            }
#pragma unroll
            for (int mi = 0; mi < 4; mi++)
#pragma unroll
                for (int ni = 0; ni < 4; ni++)
                    asm volatile(
                        "mma.sync.aligned.m16n8k8.row.col.f32.tf32.tf32.f32 "
                        "{%0,%1,%2,%3}, {%4,%5,%6,%7}, {%8,%9}, {%0,%1,%2,%3};"
                        : "+f"(acc[mi][ni][0]), "+f"(acc[mi][ni][1]),
                          "+f"(acc[mi][ni][2]), "+f"(acc[mi][ni][3])
                        : "r"(a[mi][0]), "r"(a[mi][1]), "r"(a[mi][2]), "r"(a[mi][3]),
                          "r"(bf[ni][0]), "r"(bf[ni][1]));
        }
        __syncthreads();
    }

    // Epilogue: regs -> stage[px][oc] (+bias) -> g_u2
    float* stage = dsm;
#pragma unroll
    for (int mi = 0; mi < 4; mi++) {
        int r = m0 + mi * 16 + gid;
        float bi0 = bias[m * 128 + r];
        float bi1 = bias[m * 128 + r + 8];
#pragma unroll
        for (int ni = 0; ni < 4; ni++) {
            int cn = n0 + ni * 8 + 2 * tig;
            stage[cn * 132 + r]           = acc[mi][ni][0] + bi0;
            stage[(cn + 1) * 132 + r]     = acc[mi][ni][1] + bi0;
            stage[cn * 132 + r + 8]       = acc[mi][ni][2] + bi1;
            stage[(cn + 1) * 132 + r + 8] = acc[mi][ni][3] + bi1;
        }
    }
    __syncthreads();

    const int n = b >> 3, t0 = b & 7;
#pragma unroll
    for (int k = 0; k < 16; k++) {
        int idx = tid + 256 * k;
        int p = idx >> 5, q = idx & 31;
        int h = h0 + (p >> 5), w = p & 31;
        float4 v = *(const float4*)(stage + p * 132 + q * 4);
        size_t off = ((((size_t)(n * 32 + h) * 32 + w) * 8 + t0) * 512) + m * 128 + q * 4;
        *(float4*)(g_u2 + off) = v;
    }
}

// ---------------------------------------------------------------------------
// 4) Routing iterations 0/1: u slice in registers; b update. (+pix offset)
// ---------------------------------------------------------------------------
template <int MODE>
__global__ __launch_bounds__(128) void route_kernel(int pix0) {
    __shared__ float sr[64];

    const int pix = blockIdx.x + pix0;
    const int n = pix >> 10;
    const int hw = pix & 1023;
    const int tid = threadIdx.x;
    const int t1 = tid >> 4;
    const int z4 = tid & 15;

    if (MODE >= 1 && tid < 64) {
        int rt0 = tid >> 3, rt1 = tid & 7;
        sr[tid] = g_r[((n * 8 + rt0) * 1024 + hw) * 8 + rt1];
    }

    float4 u[8];
    const float4* up = (const float4*)g_u2 + (size_t)pix * 1024 + t1 * 16 + z4;
#pragma unroll
    for (int t0 = 0; t0 < 8; t0++) u[t0] = up[t0 * 128];

    if (MODE >= 1) __syncthreads();

    float4 p = make_float4(0.f, 0.f, 0.f, 0.f);
#pragma unroll
    for (int t0 = 0; t0 < 8; t0++) {
        float r = (MODE == 0) ? 0.125f : sr[t0 * 8 + t1];
        p.x += r * u[t0].x; p.y += r * u[t0].y; p.z += r * u[t0].z; p.w += r * u[t0].w;
    }
    float n2 = p.x * p.x + p.y * p.y + p.z * p.z + p.w * p.w;
#pragma unroll
    for (int mm = 1; mm < 16; mm <<= 1) n2 += __shfl_xor_sync(0xffffffffu, n2, mm);
    float s = n2 / (1.f + n2) * rsqrtf(n2 + 1e-9f);
    float4 v = make_float4(p.x * s, p.y * s, p.z * s, p.w * s);

    float d[8];
#pragma unroll
    for (int t0 = 0; t0 < 8; t0++)
        d[t0] = u[t0].x * v.x + u[t0].y * v.y + u[t0].z * v.z + u[t0].w * v.w;
#pragma unroll
    for (int mm = 1; mm < 16; mm <<= 1) {
#pragma unroll
        for (int t0 = 0; t0 < 8; t0++)
            d[t0] += __shfl_xor_sync(0xffffffffu, d[t0], mm);
    }
    if ((tid & 15) == 0) {
#pragma unroll
        for (int t0 = 0; t0 < 8; t0++) {
            float* bp = &g_b[((n * 8 + t0) * 1024 + hw) * 8 + t1];
            if (MODE == 0) *bp = d[t0];
            else           *bp += d[t0];
        }
    }
}

// ---------------------------------------------------------------------------
// 5) r = softmax_t1(maxpool3x3(b)).  grid (band=4, nt in group), 256 thr.
// ---------------------------------------------------------------------------
__global__ __launch_bounds__(256) void pool_softmax_kernel(int nt0) {
    __shared__ float sb[10 * 32 * 8];
    const int band = blockIdx.x, nt = blockIdx.y + nt0;
    const int tid = threadIdx.x;
    const int h_base = band * 8 - 1;

    for (int i = tid; i < 640; i += 256) {
        int lr = i >> 6, rem = i & 63;
        int gh = h_base + lr;
        float4 v;
        if (gh >= 0 && gh < 32)
            v = ((const float4*)(g_b + nt * 8192 + gh * 256))[rem];
        else
            v = make_float4(-3.4e38f, -3.4e38f, -3.4e38f, -3.4e38f);
        ((float4*)sb)[i] = v;
    }
    __syncthreads();

    const int hl = tid >> 5, w = tid & 31;
    float m[8];
#pragma unroll
    for (int t = 0; t < 8; t++) m[t] = -3.4e38f;
#pragma unroll
    for (int dh = 0; dh < 3; dh++) {
        int lr = hl + dh;
#pragma unroll
        for (int dw = -1; dw <= 1; dw++) {
            int ww = w + dw;
            if (ww < 0 || ww > 31) continue;
            const float* pp = &sb[(lr * 32 + ww) * 8];
#pragma unroll
            for (int t = 0; t < 8; t++) m[t] = fmaxf(m[t], pp[t]);
        }
    }
    float mx = m[0];
#pragma unroll
    for (int t = 1; t < 8; t++) mx = fmaxf(mx, m[t]);
    float e[8], ssum = 0.f;
#pragma unroll
    for (int t = 0; t < 8; t++) { e[t] = expf(m[t] - mx); ssum += e[t]; }
    float inv = 1.f / ssum;
    float* dst = &g_r[nt * 8192 + ((band * 8 + hl) * 32 + w) * 8];
    *(float4*)(dst + 0) = make_float4(e[0] * inv, e[1] * inv, e[2] * inv, e[3] * inv);
    *(float4*)(dst + 4) = make_float4(e[4] * inv, e[5] * inv, e[6] * inv, e[7] * inv);
}

// ---------------------------------------------------------------------------
// 6) Final routing iteration fused with transpose.
//    Block = one (n,h) row, 256 threads (2 pixels per iteration, 16 iters).
//    v staged to smem [tz][w] (stride 33), then coalesced writes to out.
// ---------------------------------------------------------------------------
__global__ __launch_bounds__(256) void route2t_kernel(float* __restrict__ out, int n0) {
    extern __shared__ float vt[];            // 512 * 33 floats
    const int h = blockIdx.x;
    const int n = n0 + blockIdx.y;
    const int tid = threadIdx.x;
    const int half = tid >> 7;
    const int t1 = (tid & 127) >> 4;
    const int z4 = tid & 15;

#pragma unroll 1
    for (int wp = 0; wp < 16; wp++) {
        const int w = wp * 2 + half;
        const int hw = h * 32 + w;
        const int pix = (n * 32 + h) * 32 + w;

        float r[8];
#pragma unroll
        for (int t0 = 0; t0 < 8; t0++)
            r[t0] = g_r[((n * 8 + t0) * 1024 + hw) * 8 + t1];

        float4 p = make_float4(0.f, 0.f, 0.f, 0.f);
        const float4* up = (const float4*)g_u2 + (size_t)pix * 1024 + t1 * 16 + z4;
#pragma unroll
        for (int t0 = 0; t0 < 8; t0++) {
            float4 u = up[t0 * 128];
            p.x += r[t0] * u.x; p.y += r[t0] * u.y;
            p.z += r[t0] * u.z; p.w += r[t0] * u.w;
        }
        float n2 = p.x * p.x + p.y * p.y + p.z * p.z + p.w * p.w;
#pragma unroll
        for (int mm = 1; mm < 16; mm <<= 1) n2 += __shfl_xor_sync(0xffffffffu, n2, mm);
        float s = n2 / (1.f + n2) * rsqrtf(n2 + 1e-9f);

        const int tz = t1 * 64 + z4 * 4;
        vt[(tz + 0) * 33 + w] = p.x * s;
        vt[(tz + 1) * 33 + w] = p.y * s;
        vt[(tz + 2) * 33 + w] = p.z * s;
        vt[(tz + 3) * 33 + w] = p.w * s;
    }
    __syncthreads();

    // coalesced write-out: each warp writes one 32-float row segment
    float* dst = out + ((size_t)n * 512) * 1024 + h * 32;
#pragma unroll
    for (int k = 0; k < 64; k++) {
        int idx = tid + 256 * k;
        int row = idx >> 5, col = idx & 31;
        dst[(size_t)row * 1024 + col] = vt[row * 33 + col];
    }
}

// ---------------------------------------------------------------------------
extern "C" void kernel_launch(void* const* d_in, const int* in_sizes, int n_in,
                              void* d_out, int out_size) {
    const float* x    = (const float*)d_in[0];
    const float* W    = (const float*)d_in[1];
    const float* bias = (const float*)d_in[2];
    float* out = (float*)d_out;

    cudaFuncSetAttribute(conv_mma_kernel,
                         cudaFuncAttributeMaxDynamicSharedMemorySize, 4 * TILE_F * 4);
    cudaFuncSetAttribute(route2t_kernel,
                         cudaFuncAttributeMaxDynamicSharedMemorySize, 512 * 33 * 4);

    xt_kernel<<<dim3(64, 64), 256>>>(x);
    w2_kernel<<<576, 256>>>(W);

    // two batch groups of n=4 each: u_hat slice (64MB) stays L2-resident
    for (int g = 0; g < 2; g++) {
        conv_mma_kernel<<<dim3(8, 4, 32), 256, 4 * TILE_F * 4>>>(bias, g * 32);
        route_kernel<0><<<4096, 128>>>(g * 4096);
        pool_softmax_kernel<<<dim3(4, 32), 256>>>(g * 32);
        route_kernel<1><<<4096, 128>>>(g * 4096);
        pool_softmax_kernel<<<dim3(4, 32), 256>>>(g * 32);
        route2t_kernel<<<dim3(32, 4), 256, 512 * 33 * 4>>>(out, g * 4);
    }
}

// round 10
// speedup vs baseline: 1.1255x; 1.1255x over previous
#include <cuda_runtime.h>
#include <cstdint>

// CapsuleLayer: conv(stride2,3x3) via mma.sync tf32, 3x dynamic routing,
// final routing iteration fused with the output transpose.
// x: [8,8,32,64,64] fp32   W: [512,32,3,3]   bias: [512]
// out: [8,8,64,32,32] (N,T1,Z1,H1,W1) fp32

#define DEVINL __device__ __forceinline__

DEVINL uint32_t smem_u32(const void* p) {
    uint32_t a;
    asm("{ .reg .u64 t; cvta.to.shared.u64 t, %1; cvt.u32.u64 %0, t; }" : "=r"(a) : "l"(p));
    return a;
}
DEVINL void cp16(uint32_t dst, const void* src) {
    asm volatile("cp.async.cg.shared.global [%0], [%1], 16;" ::"r"(dst), "l"(src) : "memory");
}

// ---------------------------------------------------------------------------
__device__ __align__(128) float g_xt[64 * 66 * 66 * 32];        // NHWC padded, tf32
__device__ __align__(128) float g_w2[9 * 512 * 32];             // [kpos][oc][ic], tf32
__device__ __align__(128) float g_u2[8 * 32 * 32 * 8 * 8 * 64]; // [n][h][w][t0][t1][z]
__device__ __align__(128) float g_b [8 * 8 * 32 * 32 * 8];      // [n][t0][h][w][t1]
__device__ __align__(128) float g_r [8 * 8 * 32 * 32 * 8];

// ---------------------------------------------------------------------------
// 1) x -> g_xt  (NCHW -> padded NHWC, tf32 rounding)
// ---------------------------------------------------------------------------
__global__ __launch_bounds__(256) void xt_kernel(const float* __restrict__ x) {
    __shared__ float s[64 * 33];
    const int b = blockIdx.y, h0 = blockIdx.x;
    const int t = threadIdx.x;
    const int lane = t & 31, icg = t >> 5;
    const float* xp = x + ((size_t)(b * 32) * 64 + h0) * 64;
#pragma unroll
    for (int i = 0; i < 4; i++) {
        int ic = icg + 8 * i;
        s[lane * 33 + ic]        = xp[(size_t)ic * 4096 + lane];
        s[(lane + 32) * 33 + ic] = xp[(size_t)ic * 4096 + lane + 32];
    }
    __syncthreads();
    uint32_t* dst = (uint32_t*)(g_xt + (((size_t)b * 66 + h0 + 1) * 66 + 1) * 32);
#pragma unroll
    for (int i = 0; i < 8; i++) {
        int idx = t + 256 * i;
        int w0 = idx >> 5, ic = idx & 31;
        uint32_t u;
        asm("cvt.rna.tf32.f32 %0, %1;" : "=r"(u) : "f"(s[w0 * 33 + ic]));
        dst[idx] = u;
    }
}

// ---------------------------------------------------------------------------
// 2) W -> g_w2 [kpos][oc][ic] tf32
// ---------------------------------------------------------------------------
__global__ void w2_kernel(const float* __restrict__ W) {
    int idx = blockIdx.x * 256 + threadIdx.x;   // oc*288 + ic*9 + kp
    if (idx >= 512 * 288) return;
    int oc = idx / 288, r = idx % 288, ic = r / 9, kp = r % 9;
    uint32_t u;
    asm("cvt.rna.tf32.f32 %0, %1;" : "=r"(u) : "f"(W[idx]));
    ((uint32_t*)g_w2)[((size_t)kp * 512 + oc) * 32 + ic] = u;
}

// ---------------------------------------------------------------------------
// 3) conv via mma.sync tf32: D[oc=128][px=128] = sum_{9 kpos, 32 ic} W·X
//    grid (ptile=8, m=4, b=64), 256 threads, 2 CTAs/SM, double-buffered.
// ---------------------------------------------------------------------------
#define TSTRIDE 36
#define TILE_F  (128 * TSTRIDE)

__global__ __launch_bounds__(256, 2) void conv_mma_kernel(const float* __restrict__ bias) {
    extern __shared__ float dsm[];
    const uint32_t sbase = smem_u32(dsm);
    const uint32_t offA[2] = {0u, 2u * TILE_F * 4u};
    const uint32_t offB[2] = {TILE_F * 4u, 3u * TILE_F * 4u};

    const int tid = threadIdx.x;
    const int wid = tid >> 5, lane = tid & 31;
    const int gid = lane >> 2, tig = lane & 3;

    const int pt = blockIdx.x;    // pixel tile (4 output rows)
    const int m  = blockIdx.y;    // oc block of 128
    const int b  = blockIdx.z;    // n*8 + t0
    const int h0 = pt * 4;

    const int m0 = (wid & 1) * 64;
    const int n0 = (wid >> 1) * 32;

    float acc[4][4][4];
#pragma unroll
    for (int mi = 0; mi < 4; mi++)
#pragma unroll
        for (int ni = 0; ni < 4; ni++)
#pragma unroll
            for (int j = 0; j < 4; j++) acc[mi][ni][j] = 0.f;

    auto issue = [&](int s, int buf) {
        const int kh = s / 3, kw = s % 3;
        const float4* Asrc = (const float4*)g_w2 + ((size_t)s * 512 + m * 128) * 8;
        const int ihb = 2 * h0 + kh;
#pragma unroll
        for (int i = 0; i < 4; i++) {
            int c = tid + 256 * i;
            int o = c >> 3, q = c & 7;
            cp16(sbase + offA[buf] + (o * TSTRIDE + q * 4) * 4, Asrc + c);
            int hl = o >> 5, wl = o & 31;
            const float4* src =
                (const float4*)g_xt + (((size_t)b * 66 + ihb + 2 * hl) * 66 + 2 * wl + kw) * 8 + q;
            cp16(sbase + offB[buf] + (o * TSTRIDE + q * 4) * 4, src);
        }
        asm volatile("cp.async.commit_group;");
    };

    issue(0, 0);

    for (int s = 0; s < 9; s++) {
        if (s < 8) {
            issue(s + 1, (s + 1) & 1);
            asm volatile("cp.async.wait_group 1;" ::: "memory");
        } else {
            asm volatile("cp.async.wait_group 0;" ::: "memory");
        }
        __syncthreads();

        const uint32_t* sA = (const uint32_t*)dsm + offA[s & 1] / 4;
        const uint32_t* sB = (const uint32_t*)dsm + offB[s & 1] / 4;

#pragma unroll
        for (int kk = 0; kk < 4; kk++) {
            const int kc = kk * 8 + tig;
            uint32_t a[4][4];
#pragma unroll
            for (int mi = 0; mi < 4; mi++) {
                int r = m0 + mi * 16 + gid;
                a[mi][0] = sA[r * TSTRIDE + kc];
                a[mi][1] = sA[(r + 8) * TSTRIDE + kc];
                a[mi][2] = sA[r * TSTRIDE + kc + 4];
                a[mi][3] = sA[(r + 8) * TSTRIDE + kc + 4];
            }
            uint32_t bf[4][2];
#pragma unroll
            for (int ni = 0; ni < 4; ni++) {
                int cn = n0 + ni * 8 + gid;
                bf[ni][0] = sB[cn * TSTRIDE + kc];
                bf[ni][1] = sB[cn * TSTRIDE + kc + 4];
            }
#pragma unroll
            for (int mi = 0; mi < 4; mi++)
#pragma unroll
                for (int ni = 0; ni < 4; ni++)
                    asm volatile(
                        "mma.sync.aligned.m16n8k8.row.col.f32.tf32.tf32.f32 "
                        "{%0,%1,%2,%3}, {%4,%5,%6,%7}, {%8,%9}, {%0,%1,%2,%3};"
                        : "+f"(acc[mi][ni][0]), "+f"(acc[mi][ni][1]),
                          "+f"(acc[mi][ni][2]), "+f"(acc[mi][ni][3])
                        : "r"(a[mi][0]), "r"(a[mi][1]), "r"(a[mi][2]), "r"(a[mi][3]),
                          "r"(bf[ni][0]), "r"(bf[ni][1]));
        }
        __syncthreads();
    }

    // Epilogue: regs -> stage[px][oc] (+bias) -> g_u2
    float* stage = dsm;
#pragma unroll
    for (int mi = 0; mi < 4; mi++) {
        int r = m0 + mi * 16 + gid;
        float bi0 = bias[m * 128 + r];
        float bi1 = bias[m * 128 + r + 8];
#pragma unroll
        for (int ni = 0; ni < 4; ni++) {
            int cn = n0 + ni * 8 + 2 * tig;
            stage[cn * 132 + r]           = acc[mi][ni][0] + bi0;
            stage[(cn + 1) * 132 + r]     = acc[mi][ni][1] + bi0;
            stage[cn * 132 + r + 8]       = acc[mi][ni][2] + bi1;
            stage[(cn + 1) * 132 + r + 8] = acc[mi][ni][3] + bi1;
        }
    }
    __syncthreads();

    const int n = b >> 3, t0 = b & 7;
#pragma unroll
    for (int k = 0; k < 16; k++) {
        int idx = tid + 256 * k;
        int p = idx >> 5, q = idx & 31;
        int h = h0 + (p >> 5), w = p & 31;
        float4 v = *(const float4*)(stage + p * 132 + q * 4);
        size_t off = ((((size_t)(n * 32 + h) * 32 + w) * 8 + t0) * 512) + m * 128 + q * 4;
        *(float4*)(g_u2 + off) = v;
    }
}

// ---------------------------------------------------------------------------
// 4) Routing iterations 0/1: u slice in registers; b update.
// ---------------------------------------------------------------------------
template <int MODE>
__global__ __launch_bounds__(128) void route_kernel() {
    __shared__ float sr[64];

    const int pix = blockIdx.x;
    const int n = pix >> 10;
    const int hw = pix & 1023;
    const int tid = threadIdx.x;
    const int t1 = tid >> 4;
    const int z4 = tid & 15;

    if (MODE >= 1 && tid < 64) {
        int rt0 = tid >> 3, rt1 = tid & 7;
        sr[tid] = g_r[((n * 8 + rt0) * 1024 + hw) * 8 + rt1];
    }

    float4 u[8];
    const float4* up = (const float4*)g_u2 + (size_t)pix * 1024 + t1 * 16 + z4;
#pragma unroll
    for (int t0 = 0; t0 < 8; t0++) u[t0] = up[t0 * 128];

    if (MODE >= 1) __syncthreads();

    float4 p = make_float4(0.f, 0.f, 0.f, 0.f);
#pragma unroll
    for (int t0 = 0; t0 < 8; t0++) {
        float r = (MODE == 0) ? 0.125f : sr[t0 * 8 + t1];
        p.x += r * u[t0].x; p.y += r * u[t0].y; p.z += r * u[t0].z; p.w += r * u[t0].w;
    }
    float n2 = p.x * p.x + p.y * p.y + p.z * p.z + p.w * p.w;
#pragma unroll
    for (int mm = 1; mm < 16; mm <<= 1) n2 += __shfl_xor_sync(0xffffffffu, n2, mm);
    float s = n2 / (1.f + n2) * rsqrtf(n2 + 1e-9f);
    float4 v = make_float4(p.x * s, p.y * s, p.z * s, p.w * s);

    float d[8];
#pragma unroll
    for (int t0 = 0; t0 < 8; t0++)
        d[t0] = u[t0].x * v.x + u[t0].y * v.y + u[t0].z * v.z + u[t0].w * v.w;
#pragma unroll
    for (int mm = 1; mm < 16; mm <<= 1) {
#pragma unroll
        for (int t0 = 0; t0 < 8; t0++)
            d[t0] += __shfl_xor_sync(0xffffffffu, d[t0], mm);
    }
    if ((tid & 15) == 0) {
#pragma unroll
        for (int t0 = 0; t0 < 8; t0++) {
            float* bp = &g_b[((n * 8 + t0) * 1024 + hw) * 8 + t1];
            if (MODE == 0) *bp = d[t0];
            else           *bp += d[t0];
        }
    }
}

// ---------------------------------------------------------------------------
// 5) r = softmax_t1(maxpool3x3(b)).  grid (band=4, nt=64), 256 thr, h-banded.
// ---------------------------------------------------------------------------
__global__ __launch_bounds__(256) void pool_softmax_kernel() {
    __shared__ float sb[10 * 32 * 8];
    const int band = blockIdx.x, nt = blockIdx.y;
    const int tid = threadIdx.x;
    const int h_base = band * 8 - 1;

    for (int i = tid; i < 640; i += 256) {
        int lr = i >> 6, rem = i & 63;
        int gh = h_base + lr;
        float4 v;
        if (gh >= 0 && gh < 32)
            v = ((const float4*)(g_b + nt * 8192 + gh * 256))[rem];
        else
            v = make_float4(-3.4e38f, -3.4e38f, -3.4e38f, -3.4e38f);
        ((float4*)sb)[i] = v;
    }
    __syncthreads();

    const int hl = tid >> 5, w = tid & 31;
    float m[8];
#pragma unroll
    for (int t = 0; t < 8; t++) m[t] = -3.4e38f;
#pragma unroll
    for (int dh = 0; dh < 3; dh++) {
        int lr = hl + dh;
#pragma unroll
        for (int dw = -1; dw <= 1; dw++) {
            int ww = w + dw;
            if (ww < 0 || ww > 31) continue;
            const float* pp = &sb[(lr * 32 + ww) * 8];
#pragma unroll
            for (int t = 0; t < 8; t++) m[t] = fmaxf(m[t], pp[t]);
        }
    }
    float mx = m[0];
#pragma unroll
    for (int t = 1; t < 8; t++) mx = fmaxf(mx, m[t]);
    float e[8], ssum = 0.f;
#pragma unroll
    for (int t = 0; t < 8; t++) { e[t] = expf(m[t] - mx); ssum += e[t]; }
    float inv = 1.f / ssum;
    float* dst = &g_r[nt * 8192 + ((band * 8 + hl) * 32 + w) * 8];
    *(float4*)(dst + 0) = make_float4(e[0] * inv, e[1] * inv, e[2] * inv, e[3] * inv);
    *(float4*)(dst + 4) = make_float4(e[4] * inv, e[5] * inv, e[6] * inv, e[7] * inv);
}

// ---------------------------------------------------------------------------
// 6) Final routing iteration fused with transpose.
//    Block = 8 pixels of one (n,h) row; grid (4, 32, 8) = 1024 blocks, 256 thr.
//    v staged to smem vt[wl][tz] (stride 516), then float2 row writes into
//    out[n][tz][h*32+w0..w0+7] (32B-aligned sectors).
// ---------------------------------------------------------------------------
__global__ __launch_bounds__(256) void route2t_kernel(float* __restrict__ out) {
    __shared__ float vt[8 * 516];
    const int wq = blockIdx.x;          // quarter-row
    const int h  = blockIdx.y;
    const int n  = blockIdx.z;
    const int tid = threadIdx.x;
    const int half = tid >> 7;
    const int t1 = (tid & 127) >> 4;
    const int z4 = tid & 15;
    const int w0 = wq * 8;

#pragma unroll
    for (int wp = 0; wp < 4; wp++) {
        const int wl = wp * 2 + half;
        const int w = w0 + wl;
        const int hw = h * 32 + w;
        const int pix = (n * 32 + h) * 32 + w;

        float r[8];
#pragma unroll
        for (int t0 = 0; t0 < 8; t0++)
            r[t0] = g_r[((n * 8 + t0) * 1024 + hw) * 8 + t1];

        float4 p = make_float4(0.f, 0.f, 0.f, 0.f);
        const float4* up = (const float4*)g_u2 + (size_t)pix * 1024 + t1 * 16 + z4;
#pragma unroll
        for (int t0 = 0; t0 < 8; t0++) {
            float4 u = up[t0 * 128];
            p.x += r[t0] * u.x; p.y += r[t0] * u.y;
            p.z += r[t0] * u.z; p.w += r[t0] * u.w;
        }
        float n2 = p.x * p.x + p.y * p.y + p.z * p.z + p.w * p.w;
#pragma unroll
        for (int mm = 1; mm < 16; mm <<= 1) n2 += __shfl_xor_sync(0xffffffffu, n2, mm);
        float s = n2 / (1.f + n2) * rsqrtf(n2 + 1e-9f);

        *(float4*)&vt[wl * 516 + t1 * 64 + z4 * 4] =
            make_float4(p.x * s, p.y * s, p.z * s, p.w * s);
    }
    __syncthreads();

    // write out: 512 tz-rows x 8 cols; each thread does one 8B float2 per iter
    float* dst = out + (size_t)n * 512 * 1024 + h * 32 + w0;
#pragma unroll
    for (int k = 0; k < 8; k++) {
        int idx = tid + 256 * k;            // 0..2047 float2 slots
        int row = idx >> 2, col2 = idx & 3; // 512 rows x 4 float2-cols
        float2 v2 = make_float2(vt[(col2 * 2 + 0) * 516 + row],
                                vt[(col2 * 2 + 1) * 516 + row]);
        *(float2*)(dst + (size_t)row * 1024 + col2 * 2) = v2;
    }
}

// ---------------------------------------------------------------------------
extern "C" void kernel_launch(void* const* d_in, const int* in_sizes, int n_in,
                              void* d_out, int out_size) {
    const float* x    = (const float*)d_in[0];
    const float* W    = (const float*)d_in[1];
    const float* bias = (const float*)d_in[2];
    float* out = (float*)d_out;

    cudaFuncSetAttribute(conv_mma_kernel,
                         cudaFuncAttributeMaxDynamicSharedMemorySize, 4 * TILE_F * 4);

    xt_kernel<<<dim3(64, 64), 256>>>(x);
    w2_kernel<<<576, 256>>>(W);
    conv_mma_kernel<<<dim3(8, 4, 64), 256, 4 * TILE_F * 4>>>(bias);

    route_kernel<0><<<8192, 128>>>();
    pool_softmax_kernel<<<dim3(4, 64), 256>>>();
    route_kernel<1><<<8192, 128>>>();
    pool_softmax_kernel<<<dim3(4, 64), 256>>>();
    route2t_kernel<<<dim3(4, 32, 8), 256>>>(out);
}

// round 11
// speedup vs baseline: 1.1449x; 1.0172x over previous
#include <cuda_runtime.h>
#include <cstdint>

// CapsuleLayer: conv(stride2,3x3) via mma.sync tf32 (resident-X region),
// 3x dynamic routing, final routing iteration fused with output transpose.
// x: [8,8,32,64,64] fp32   W: [512,32,3,3]   bias: [512]
// out: [8,8,64,32,32] (N,T1,Z1,H1,W1) fp32

#define DEVINL __device__ __forceinline__

DEVINL uint32_t smem_u32(const void* p) {
    uint32_t a;
    asm("{ .reg .u64 t; cvta.to.shared.u64 t, %1; cvt.u32.u64 %0, t; }" : "=r"(a) : "l"(p));
    return a;
}
DEVINL void cp16(uint32_t dst, const void* src) {
    asm volatile("cp.async.cg.shared.global [%0], [%1], 16;" ::"r"(dst), "l"(src) : "memory");
}
DEVINL void cp8(uint32_t dst, const void* src) {
    asm volatile("cp.async.ca.shared.global [%0], [%1], 8;" ::"r"(dst), "l"(src) : "memory");
}

// ---------------------------------------------------------------------------
__device__ __align__(128) float g_xt[64 * 66 * 66 * 32];        // NHWC padded, tf32
__device__ __align__(128) float g_w2[9 * 512 * 32];             // [kpos][oc][ic], tf32
__device__ __align__(128) float g_u2[8 * 32 * 32 * 8 * 8 * 64]; // [n][h][w][t0][t1][z]
__device__ __align__(128) float g_b [8 * 8 * 32 * 32 * 8];      // [n][t0][h][w][t1]
__device__ __align__(128) float g_r [8 * 8 * 32 * 32 * 8];

// ---------------------------------------------------------------------------
// 1) x -> g_xt  (NCHW -> padded NHWC, tf32 rounding)
// ---------------------------------------------------------------------------
__global__ __launch_bounds__(256) void xt_kernel(const float* __restrict__ x) {
    __shared__ float s[64 * 33];
    const int b = blockIdx.y, h0 = blockIdx.x;
    const int t = threadIdx.x;
    const int lane = t & 31, icg = t >> 5;
    const float* xp = x + ((size_t)(b * 32) * 64 + h0) * 64;
#pragma unroll
    for (int i = 0; i < 4; i++) {
        int ic = icg + 8 * i;
        s[lane * 33 + ic]        = xp[(size_t)ic * 4096 + lane];
        s[(lane + 32) * 33 + ic] = xp[(size_t)ic * 4096 + lane + 32];
    }
    __syncthreads();
    uint32_t* dst = (uint32_t*)(g_xt + (((size_t)b * 66 + h0 + 1) * 66 + 1) * 32);
#pragma unroll
    for (int i = 0; i < 8; i++) {
        int idx = t + 256 * i;
        int w0 = idx >> 5, ic = idx & 31;
        uint32_t u;
        asm("cvt.rna.tf32.f32 %0, %1;" : "=r"(u) : "f"(s[w0 * 33 + ic]));
        dst[idx] = u;
    }
}

// ---------------------------------------------------------------------------
// 2) W -> g_w2 [kpos][oc][ic] tf32
// ---------------------------------------------------------------------------
__global__ void w2_kernel(const float* __restrict__ W) {
    int idx = blockIdx.x * 256 + threadIdx.x;   // oc*288 + ic*9 + kp
    if (idx >= 512 * 288) return;
    int oc = idx / 288, r = idx % 288, ic = r / 9, kp = r % 9;
    uint32_t u;
    asm("cvt.rna.tf32.f32 %0, %1;" : "=r"(u) : "f"(W[idx]));
    ((uint32_t*)g_w2)[((size_t)kp * 512 + oc) * 32 + ic] = u;
}

// ---------------------------------------------------------------------------
// 3) conv via mma.sync tf32.  CTA tile: 128 oc x 256 px (8 output rows).
//    X region (17 rows x 66 cols x 32 ic, pixel stride 34 floats) loaded ONCE;
//    B fragments indexed directly from it for all 9 (kh,kw) stages.
//    A (weights) double-buffered via cp.async, 16KB/stage.
//    Warp tile 64x64: acc[4][8][4] = 128 regs.
// ---------------------------------------------------------------------------
#define XSTR 34                            // floats per pixel row in smem
#define XPIX (17 * 66)
#define ASTR 36
#define AOFF0 152832                       // 128B-aligned, > XPIX*XSTR*4=152592
#define ABYTES (128 * ASTR * 4)            // 18432
#define AOFF1 (AOFF0 + ABYTES)
#define CONV_SMEM (AOFF1 + ABYTES)         // 189696

__global__ __launch_bounds__(256, 1) void conv_mma_kernel(const float* __restrict__ bias) {
    extern __shared__ float dsm[];
    const uint32_t sbase = smem_u32(dsm);
    const uint32_t offA[2] = {AOFF0, AOFF1};

    const int tid = threadIdx.x;
    const int wid = tid >> 5, lane = tid & 31;
    const int gid = lane >> 2, tig = lane & 3;

    const int pt = blockIdx.x;    // 8 output rows
    const int m  = blockIdx.y;    // oc block of 128
    const int b  = blockIdx.z;    // n*8 + t0
    const int h0 = pt * 8;

    const int m0 = (wid & 1) * 64;       // warp oc base
    const int n0 = (wid >> 1) * 64;      // warp pixel base (64 px = 2 rows)

    int xoff[8];
#pragma unroll
    for (int ni = 0; ni < 8; ni++) {
        int cn = n0 + ni * 8 + gid;
        int hl = cn >> 5, wl = cn & 31;
        xoff[ni] = (2 * hl * 66 + 2 * wl) * XSTR;
    }

    float acc[4][8][4];
#pragma unroll
    for (int mi = 0; mi < 4; mi++)
#pragma unroll
        for (int ni = 0; ni < 8; ni++)
#pragma unroll
            for (int j = 0; j < 4; j++) acc[mi][ni][j] = 0.f;

    // ---- one-time X region load: 17x66 pixels, 128B each as 16x 8B chunks
    {
        const char* xsrc = (const char*)(g_xt + ((size_t)b * 66 + 2 * h0) * 66 * 32);
        for (int i = tid; i < XPIX * 16; i += 256) {
            int px = i >> 4, q = i & 15;
            cp8(sbase + px * (XSTR * 4) + q * 8, xsrc + (size_t)px * 128 + q * 8);
        }
    }
    // ---- A stage issue
    auto issueA = [&](int s, int buf) {
        const float4* Asrc = (const float4*)g_w2 + ((size_t)s * 512 + m * 128) * 8;
#pragma unroll
        for (int i = 0; i < 4; i++) {
            int c = tid + 256 * i;
            int o = c >> 3, q = c & 7;
            cp16(sbase + offA[buf] + (o * ASTR + q * 4) * 4, Asrc + c);
        }
        asm volatile("cp.async.commit_group;");
    };

    issueA(0, 0);   // group0 = X region + A0
    issueA(1, 1);   // group1 = A1

    for (int s = 0; s < 9; s++) {
        if (s < 8) asm volatile("cp.async.wait_group 1;" ::: "memory");
        else       asm volatile("cp.async.wait_group 0;" ::: "memory");
        __syncthreads();

        const int kh = s / 3, kw = s % 3;
        const int soff = (kh * 66 + kw) * XSTR;
        const float* sA = dsm + (offA[s & 1] >> 2);

#pragma unroll
        for (int kk = 0; kk < 4; kk++) {
            const int kc = kk * 8 + tig;
            uint32_t a[4][4];
#pragma unroll
            for (int mi = 0; mi < 4; mi++) {
                int r = m0 + mi * 16 + gid;
                a[mi][0] = __float_as_uint(sA[r * ASTR + kc]);
                a[mi][1] = __float_as_uint(sA[(r + 8) * ASTR + kc]);
                a[mi][2] = __float_as_uint(sA[r * ASTR + kc + 4]);
                a[mi][3] = __float_as_uint(sA[(r + 8) * ASTR + kc + 4]);
            }
            uint32_t bf[8][2];
#pragma unroll
            for (int ni = 0; ni < 8; ni++) {
                const float* bp = dsm + xoff[ni] + soff + kc;
                bf[ni][0] = __float_as_uint(bp[0]);
                bf[ni][1] = __float_as_uint(bp[4]);
            }
#pragma unroll
            for (int mi = 0; mi < 4; mi++)
#pragma unroll
                for (int ni = 0; ni < 8; ni++) {
                    float* A = acc[mi][ni];
                    asm volatile(
                        "mma.sync.aligned.m16n8k8.row.col.f32.tf32.tf32.f32 "
                        "{%0,%1,%2,%3}, {%4,%5,%6,%7}, {%8,%9}, {%0,%1,%2,%3};"
                        : "+f"(A[0]), "+f"(A[1]), "+f"(A[2]), "+f"(A[3])
                        : "r"(a[mi][0]), "r"(a[mi][1]), "r"(a[mi][2]), "r"(a[mi][3]),
                          "r"(bf[ni][0]), "r"(bf[ni][1]));
                }
        }
        __syncthreads();
        if (s < 7) issueA(s + 2, s & 1);
    }

    // ---- epilogue: regs -> stage[px][oc] (+bias) -> g_u2
    float* stage = dsm;    // 256*132*4 = 135168 <= X region bytes
#pragma unroll
    for (int mi = 0; mi < 4; mi++) {
        int r = m0 + mi * 16 + gid;
        float bi0 = bias[m * 128 + r];
        float bi1 = bias[m * 128 + r + 8];
#pragma unroll
        for (int ni = 0; ni < 8; ni++) {
            int cn = n0 + ni * 8 + 2 * tig;
            stage[cn * 132 + r]           = acc[mi][ni][0] + bi0;
            stage[(cn + 1) * 132 + r]     = acc[mi][ni][1] + bi0;
            stage[cn * 132 + r + 8]       = acc[mi][ni][2] + bi1;
            stage[(cn + 1) * 132 + r + 8] = acc[mi][ni][3] + bi1;
        }
    }
    __syncthreads();

    const int n = b >> 3, t0 = b & 7;
#pragma unroll
    for (int k = 0; k < 32; k++) {
        int idx = tid + 256 * k;          // 8192 float4 = 256 px * 32
        int p = idx >> 5, q = idx & 31;
        int h = h0 + (p >> 5), w = p & 31;
        float4 v = *(const float4*)(stage + p * 132 + q * 4);
        size_t off = ((((size_t)(n * 32 + h) * 32 + w) * 8 + t0) * 512) + m * 128 + q * 4;
        *(float4*)(g_u2 + off) = v;
    }
}

// ---------------------------------------------------------------------------
// 4) Routing iterations 0/1: u slice in registers; b update.
// ---------------------------------------------------------------------------
template <int MODE>
__global__ __launch_bounds__(128) void route_kernel() {
    __shared__ float sr[64];

    const int pix = blockIdx.x;
    const int n = pix >> 10;
    const int hw = pix & 1023;
    const int tid = threadIdx.x;
    const int t1 = tid >> 4;
    const int z4 = tid & 15;

    if (MODE >= 1 && tid < 64) {
        int rt0 = tid >> 3, rt1 = tid & 7;
        sr[tid] = g_r[((n * 8 + rt0) * 1024 + hw) * 8 + rt1];
    }

    float4 u[8];
    const float4* up = (const float4*)g_u2 + (size_t)pix * 1024 + t1 * 16 + z4;
#pragma unroll
    for (int t0 = 0; t0 < 8; t0++) u[t0] = up[t0 * 128];

    if (MODE >= 1) __syncthreads();

    float4 p = make_float4(0.f, 0.f, 0.f, 0.f);
#pragma unroll
    for (int t0 = 0; t0 < 8; t0++) {
        float r = (MODE == 0) ? 0.125f : sr[t0 * 8 + t1];
        p.x += r * u[t0].x; p.y += r * u[t0].y; p.z += r * u[t0].z; p.w += r * u[t0].w;
    }
    float n2 = p.x * p.x + p.y * p.y + p.z * p.z + p.w * p.w;
#pragma unroll
    for (int mm = 1; mm < 16; mm <<= 1) n2 += __shfl_xor_sync(0xffffffffu, n2, mm);
    float s = n2 / (1.f + n2) * rsqrtf(n2 + 1e-9f);
    float4 v = make_float4(p.x * s, p.y * s, p.z * s, p.w * s);

    float d[8];
#pragma unroll
    for (int t0 = 0; t0 < 8; t0++)
        d[t0] = u[t0].x * v.x + u[t0].y * v.y + u[t0].z * v.z + u[t0].w * v.w;
#pragma unroll
    for (int mm = 1; mm < 16; mm <<= 1) {
#pragma unroll
        for (int t0 = 0; t0 < 8; t0++)
            d[t0] += __shfl_xor_sync(0xffffffffu, d[t0], mm);
    }
    if ((tid & 15) == 0) {
#pragma unroll
        for (int t0 = 0; t0 < 8; t0++) {
            float* bp = &g_b[((n * 8 + t0) * 1024 + hw) * 8 + t1];
            if (MODE == 0) *bp = d[t0];
            else           *bp += d[t0];
        }
    }
}

// ---------------------------------------------------------------------------
// 5) r = softmax_t1(maxpool3x3(b)).  grid (band=4, nt=64), 256 thr, h-banded.
// ---------------------------------------------------------------------------
__global__ __launch_bounds__(256) void pool_softmax_kernel() {
    __shared__ float sb[10 * 32 * 8];
    const int band = blockIdx.x, nt = blockIdx.y;
    const int tid = threadIdx.x;
    const int h_base = band * 8 - 1;

    for (int i = tid; i < 640; i += 256) {
        int lr = i >> 6, rem = i & 63;
        int gh = h_base + lr;
        float4 v;
        if (gh >= 0 && gh < 32)
            v = ((const float4*)(g_b + nt * 8192 + gh * 256))[rem];
        else
            v = make_float4(-3.4e38f, -3.4e38f, -3.4e38f, -3.4e38f);
        ((float4*)sb)[i] = v;
    }
    __syncthreads();

    const int hl = tid >> 5, w = tid & 31;
    float m[8];
#pragma unroll
    for (int t = 0; t < 8; t++) m[t] = -3.4e38f;
#pragma unroll
    for (int dh = 0; dh < 3; dh++) {
        int lr = hl + dh;
#pragma unroll
        for (int dw = -1; dw <= 1; dw++) {
            int ww = w + dw;
            if (ww < 0 || ww > 31) continue;
            const float* pp = &sb[(lr * 32 + ww) * 8];
#pragma unroll
            for (int t = 0; t < 8; t++) m[t] = fmaxf(m[t], pp[t]);
        }
    }
    float mx = m[0];
#pragma unroll
    for (int t = 1; t < 8; t++) mx = fmaxf(mx, m[t]);
    float e[8], ssum = 0.f;
#pragma unroll
    for (int t = 0; t < 8; t++) { e[t] = expf(m[t] - mx); ssum += e[t]; }
    float inv = 1.f / ssum;
    float* dst = &g_r[nt * 8192 + ((band * 8 + hl) * 32 + w) * 8];
    *(float4*)(dst + 0) = make_float4(e[0] * inv, e[1] * inv, e[2] * inv, e[3] * inv);
    *(float4*)(dst + 4) = make_float4(e[4] * inv, e[5] * inv, e[6] * inv, e[7] * inv);
}

// ---------------------------------------------------------------------------
// 6) Final routing iteration fused with transpose.
//    Block = 8 pixels of one (n,h) row; grid (4, 32, 8) = 1024 blocks, 256 thr.
// ---------------------------------------------------------------------------
__global__ __launch_bounds__(256) void route2t_kernel(float* __restrict__ out) {
    __shared__ float vt[8 * 516];
    const int wq = blockIdx.x;          // quarter-row
    const int h  = blockIdx.y;
    const int n  = blockIdx.z;
    const int tid = threadIdx.x;
    const int half = tid >> 7;
    const int t1 = (tid & 127) >> 4;
    const int z4 = tid & 15;
    const int w0 = wq * 8;

#pragma unroll
    for (int wp = 0; wp < 4; wp++) {
        const int wl = wp * 2 + half;
        const int w = w0 + wl;
        const int hw = h * 32 + w;
        const int pix = (n * 32 + h) * 32 + w;

        float r[8];
#pragma unroll
        for (int t0 = 0; t0 < 8; t0++)
            r[t0] = g_r[((n * 8 + t0) * 1024 + hw) * 8 + t1];

        float4 p = make_float4(0.f, 0.f, 0.f, 0.f);
        const float4* up = (const float4*)g_u2 + (size_t)pix * 1024 + t1 * 16 + z4;
#pragma unroll
        for (int t0 = 0; t0 < 8; t0++) {
            float4 u = up[t0 * 128];
            p.x += r[t0] * u.x; p.y += r[t0] * u.y;
            p.z += r[t0] * u.z; p.w += r[t0] * u.w;
        }
        float n2 = p.x * p.x + p.y * p.y + p.z * p.z + p.w * p.w;
#pragma unroll
        for (int mm = 1; mm < 16; mm <<= 1) n2 += __shfl_xor_sync(0xffffffffu, n2, mm);
        float s = n2 / (1.f + n2) * rsqrtf(n2 + 1e-9f);

        *(float4*)&vt[wl * 516 + t1 * 64 + z4 * 4] =
            make_float4(p.x * s, p.y * s, p.z * s, p.w * s);
    }
    __syncthreads();

    float* dst = out + (size_t)n * 512 * 1024 + h * 32 + w0;
#pragma unroll
    for (int k = 0; k < 8; k++) {
        int idx = tid + 256 * k;            // 0..2047 float2 slots
        int row = idx >> 2, col2 = idx & 3; // 512 rows x 4 float2-cols
        float2 v2 = make_float2(vt[(col2 * 2 + 0) * 516 + row],
                                vt[(col2 * 2 + 1) * 516 + row]);
        *(float2*)(dst + (size_t)row * 1024 + col2 * 2) = v2;
    }
}

// ---------------------------------------------------------------------------
extern "C" void kernel_launch(void* const* d_in, const int* in_sizes, int n_in,
                              void* d_out, int out_size) {
    const float* x    = (const float*)d_in[0];
    const float* W    = (const float*)d_in[1];
    const float* bias = (const float*)d_in[2];
    float* out = (float*)d_out;

    cudaFuncSetAttribute(conv_mma_kernel,
                         cudaFuncAttributeMaxDynamicSharedMemorySize, CONV_SMEM);

    xt_kernel<<<dim3(64, 64), 256>>>(x);
    w2_kernel<<<576, 256>>>(W);
    conv_mma_kernel<<<dim3(4, 4, 64), 256, CONV_SMEM>>>(bias);

    route_kernel<0><<<8192, 128>>>();
    pool_softmax_kernel<<<dim3(4, 64), 256>>>();
    route_kernel<1><<<8192, 128>>>();
    pool_softmax_kernel<<<dim3(4, 64), 256>>>();
    route2t_kernel<<<dim3(4, 32, 8), 256>>>(out);
}

// round 13
// speedup vs baseline: 1.3834x; 1.2084x over previous
#include <cuda_runtime.h>
#include <cuda_fp16.h>
#include <cstdint>

// CapsuleLayer: conv(stride2,3x3) via mma.sync fp16 (m16n8k16, fp32 accum),
// 3x dynamic routing, final routing iteration fused with output transpose.
// x: [8,8,32,64,64] fp32   W: [512,32,3,3]   bias: [512]
// out: [8,8,64,32,32] (N,T1,Z1,H1,W1) fp32

#define DEVINL __device__ __forceinline__

DEVINL uint32_t smem_u32(const void* p) {
    uint32_t a;
    asm("{ .reg .u64 t; cvta.to.shared.u64 t, %1; cvt.u32.u64 %0, t; }" : "=r"(a) : "l"(p));
    return a;
}
DEVINL void cp16(uint32_t dst, const void* src) {
    asm volatile("cp.async.cg.shared.global [%0], [%1], 16;" ::"r"(dst), "l"(src) : "memory");
}

// ---------------------------------------------------------------------------
__device__ __align__(128) __half g_xh[64 * 66 * 66 * 32];       // NHWC padded, fp16
__device__ __align__(128) __half g_wh[9 * 512 * 32];            // [kpos][oc][ic], fp16
__device__ __align__(128) float g_u2[8 * 32 * 32 * 8 * 8 * 64]; // [n][h][w][t0][t1][z]
__device__ __align__(128) float g_b [8 * 8 * 32 * 32 * 8];      // [n][t0][h][w][t1]
__device__ __align__(128) float g_r [8 * 8 * 32 * 32 * 8];

// ---------------------------------------------------------------------------
// 1) x -> g_xh  (NCHW -> padded NHWC, fp16)
// ---------------------------------------------------------------------------
__global__ __launch_bounds__(256) void xt_kernel(const float* __restrict__ x) {
    __shared__ float s[64 * 33];
    const int b = blockIdx.y, h0 = blockIdx.x;
    const int t = threadIdx.x;
    const int lane = t & 31, icg = t >> 5;
    const float* xp = x + ((size_t)(b * 32) * 64 + h0) * 64;
#pragma unroll
    for (int i = 0; i < 4; i++) {
        int ic = icg + 8 * i;
        s[lane * 33 + ic]        = xp[(size_t)ic * 4096 + lane];
        s[(lane + 32) * 33 + ic] = xp[(size_t)ic * 4096 + lane + 32];
    }
    __syncthreads();
    __half2* dst = (__half2*)(g_xh + (((size_t)b * 66 + h0 + 1) * 66 + 1) * 32);
#pragma unroll
    for (int i = 0; i < 4; i++) {
        int idx = t + 256 * i;              // 1024 half2 = 64 px * 16 pairs
        int w0 = idx >> 4, icp = idx & 15;
        dst[w0 * 16 + icp] = __floats2half2_rn(s[w0 * 33 + 2 * icp],
                                               s[w0 * 33 + 2 * icp + 1]);
    }
}

// ---------------------------------------------------------------------------
// 2) W -> g_wh [kpos][oc][ic] fp16
// ---------------------------------------------------------------------------
__global__ void w2_kernel(const float* __restrict__ W) {
    int idx = blockIdx.x * 256 + threadIdx.x;   // oc*288 + ic*9 + kp
    if (idx >= 512 * 288) return;
    int oc = idx / 288, r = idx % 288, ic = r / 9, kp = r % 9;
    g_wh[((size_t)kp * 512 + oc) * 32 + ic] = __float2half_rn(W[idx]);
}

// ---------------------------------------------------------------------------
// 3) conv via mma.sync fp16 m16n8k16: D[oc=128][px=128] = sum_{9 kpos,32 ic}
//    grid (ptile=8, m=4, b=64), 256 threads, 2 CTAs/SM, double-buffered A+B.
//    smem rows: 40 halves (80B) per oc/pixel; fragment banks 20*gid+tig mod 32
//    all distinct -> conflict-free.
// ---------------------------------------------------------------------------
#define RSTRB 80                     // bytes per row in smem tile
#define RSTR32 20                    // u32 stride per row
#define TILE_B (128 * RSTRB)         // 10240 bytes per tile
#define CONV_SMEM 67584              // stage[128px][132] floats dominates

__global__ __launch_bounds__(256, 2) void conv_mma_kernel(const float* __restrict__ bias) {
    extern __shared__ float dsm[];
    const uint32_t sbase = smem_u32(dsm);
    const uint32_t offA[2] = {0u, 2u * TILE_B};
    const uint32_t offB[2] = {TILE_B, 3u * TILE_B};

    const int tid = threadIdx.x;
    const int wid = tid >> 5, lane = tid & 31;
    const int gid = lane >> 2, tig = lane & 3;

    const int pt = blockIdx.x;    // pixel tile (4 output rows)
    const int m  = blockIdx.y;    // oc block of 128
    const int b  = blockIdx.z;    // n*8 + t0
    const int h0 = pt * 4;

    const int m0 = (wid & 1) * 64;
    const int n0 = (wid >> 1) * 32;

    float acc[4][4][4];
#pragma unroll
    for (int mi = 0; mi < 4; mi++)
#pragma unroll
        for (int ni = 0; ni < 4; ni++)
#pragma unroll
            for (int j = 0; j < 4; j++) acc[mi][ni][j] = 0.f;

    auto issue = [&](int s, int buf) {
        const int kh = s / 3, kw = s % 3;
        // A tile: 128 oc x 64B = 512 x 16B chunks
        const uint4* Asrc = (const uint4*)g_wh + ((size_t)s * 512 + m * 128) * 4;
        const int ihb = 2 * h0 + kh;
#pragma unroll
        for (int i = 0; i < 2; i++) {
            int c = tid + 256 * i;          // 0..511
            int o = c >> 2, q = c & 3;
            cp16(sbase + offA[buf] + o * RSTRB + q * 16, Asrc + c);
            int hl = o >> 5, wl = o & 31;
            const uint4* src =
                (const uint4*)g_xh + (((size_t)b * 66 + ihb + 2 * hl) * 66 + 2 * wl + kw) * 4 + q;
            cp16(sbase + offB[buf] + o * RSTRB + q * 16, src);
        }
        asm volatile("cp.async.commit_group;");
    };

    issue(0, 0);

    for (int s = 0; s < 9; s++) {
        if (s < 8) {
            issue(s + 1, (s + 1) & 1);
            asm volatile("cp.async.wait_group 1;" ::: "memory");
        } else {
            asm volatile("cp.async.wait_group 0;" ::: "memory");
        }
        __syncthreads();

        const uint32_t* sA = (const uint32_t*)dsm + offA[s & 1] / 4;
        const uint32_t* sB = (const uint32_t*)dsm + offB[s & 1] / 4;

#pragma unroll
        for (int kk = 0; kk < 2; kk++) {    // two 16-ic chunks per stage
            const int kc = kk * 8 + tig;
            uint32_t a[4][4];
#pragma unroll
            for (int mi = 0; mi < 4; mi++) {
                int r = m0 + mi * 16 + gid;
                a[mi][0] = sA[r * RSTR32 + kc];
                a[mi][1] = sA[(r + 8) * RSTR32 + kc];
                a[mi][2] = sA[r * RSTR32 + kc + 4];
                a[mi][3] = sA[(r + 8) * RSTR32 + kc + 4];
            }
            uint32_t bf[4][2];
#pragma unroll
            for (int ni = 0; ni < 4; ni++) {
                int cn = n0 + ni * 8 + gid;
                bf[ni][0] = sB[cn * RSTR32 + kc];
                bf[ni][1] = sB[cn * RSTR32 + kc + 4];
            }
#pragma unroll
            for (int mi = 0; mi < 4; mi++)
#pragma unroll
                for (int ni = 0; ni < 4; ni++)
                    asm volatile(
                        "mma.sync.aligned.m16n8k16.row.col.f32.f16.f16.f32 "
                        "{%0,%1,%2,%3}, {%4,%5,%6,%7}, {%8,%9}, {%0,%1,%2,%3};"
                        : "+f"(acc[mi][ni][0]), "+f"(acc[mi][ni][1]),
                          "+f"(acc[mi][ni][2]), "+f"(acc[mi][ni][3])
                        : "r"(a[mi][0]), "r"(a[mi][1]), "r"(a[mi][2]), "r"(a[mi][3]),
                          "r"(bf[ni][0]), "r"(bf[ni][1]));
        }
        __syncthreads();
    }

    // Epilogue: regs -> stage[px][oc] (+bias) -> g_u2
    float* stage = dsm;
#pragma unroll
    for (int mi = 0; mi < 4; mi++) {
        int r = m0 + mi * 16 + gid;
        float bi0 = bias[m * 128 + r];
        float bi1 = bias[m * 128 + r + 8];
#pragma unroll
        for (int ni = 0; ni < 4; ni++) {
            int cn = n0 + ni * 8 + 2 * tig;
            stage[cn * 132 + r]           = acc[mi][ni][0] + bi0;
            stage[(cn + 1) * 132 + r]     = acc[mi][ni][1] + bi0;
            stage[cn * 132 + r + 8]       = acc[mi][ni][2] + bi1;
            stage[(cn + 1) * 132 + r + 8] = acc[mi][ni][3] + bi1;
        }
    }
    __syncthreads();

    const int n = b >> 3, t0 = b & 7;
#pragma unroll
    for (int k = 0; k < 16; k++) {
        int idx = tid + 256 * k;
        int p = idx >> 5, q = idx & 31;
        int h = h0 + (p >> 5), w = p & 31;
        float4 v = *(const float4*)(stage + p * 132 + q * 4);
        size_t off = ((((size_t)(n * 32 + h) * 32 + w) * 8 + t0) * 512) + m * 128 + q * 4;
        *(float4*)(g_u2 + off) = v;
    }
}

// ---------------------------------------------------------------------------
// 4) Routing iterations 0/1: u slice in registers; b update.
// ---------------------------------------------------------------------------
template <int MODE>
__global__ __launch_bounds__(128) void route_kernel() {
    __shared__ float sr[64];

    const int pix = blockIdx.x;
    const int n = pix >> 10;
    const int hw = pix & 1023;
    const int tid = threadIdx.x;
    const int t1 = tid >> 4;
    const int z4 = tid & 15;

    if (MODE >= 1 && tid < 64) {
        int rt0 = tid >> 3, rt1 = tid & 7;
        sr[tid] = g_r[((n * 8 + rt0) * 1024 + hw) * 8 + rt1];
    }

    float4 u[8];
    const float4* up = (const float4*)g_u2 + (size_t)pix * 1024 + t1 * 16 + z4;
#pragma unroll
    for (int t0 = 0; t0 < 8; t0++) u[t0] = up[t0 * 128];

    if (MODE >= 1) __syncthreads();

    float4 p = make_float4(0.f, 0.f, 0.f, 0.f);
#pragma unroll
    for (int t0 = 0; t0 < 8; t0++) {
        float r = (MODE == 0) ? 0.125f : sr[t0 * 8 + t1];
        p.x += r * u[t0].x; p.y += r * u[t0].y; p.z += r * u[t0].z; p.w += r * u[t0].w;
    }
    float n2 = p.x * p.x + p.y * p.y + p.z * p.z + p.w * p.w;
#pragma unroll
    for (int mm = 1; mm < 16; mm <<= 1) n2 += __shfl_xor_sync(0xffffffffu, n2, mm);
    float s = n2 / (1.f + n2) * rsqrtf(n2 + 1e-9f);
    float4 v = make_float4(p.x * s, p.y * s, p.z * s, p.w * s);

    float d[8];
#pragma unroll
    for (int t0 = 0; t0 < 8; t0++)
        d[t0] = u[t0].x * v.x + u[t0].y * v.y + u[t0].z * v.z + u[t0].w * v.w;
#pragma unroll
    for (int mm = 1; mm < 16; mm <<= 1) {
#pragma unroll
        for (int t0 = 0; t0 < 8; t0++)
            d[t0] += __shfl_xor_sync(0xffffffffu, d[t0], mm);
    }
    if ((tid & 15) == 0) {
#pragma unroll
        for (int t0 = 0; t0 < 8; t0++) {
            float* bp = &g_b[((n * 8 + t0) * 1024 + hw) * 8 + t1];
            if (MODE == 0) *bp = d[t0];
            else           *bp += d[t0];
        }
    }
}

// ---------------------------------------------------------------------------
// 5) r = softmax_t1(maxpool3x3(b)).  grid (band=4, nt=64), 256 thr, h-banded.
// ---------------------------------------------------------------------------
__global__ __launch_bounds__(256) void pool_softmax_kernel() {
    __shared__ float sb[10 * 32 * 8];
    const int band = blockIdx.x, nt = blockIdx.y;
    const int tid = threadIdx.x;
    const int h_base = band * 8 - 1;

    for (int i = tid; i < 640; i += 256) {
        int lr = i >> 6, rem = i & 63;
        int gh = h_base + lr;
        float4 v;
        if (gh >= 0 && gh < 32)
            v = ((const float4*)(g_b + nt * 8192 + gh * 256))[rem];
        else
            v = make_float4(-3.4e38f, -3.4e38f, -3.4e38f, -3.4e38f);
        ((float4*)sb)[i] = v;
    }
    __syncthreads();

    const int hl = tid >> 5, w = tid & 31;
    float m[8];
#pragma unroll
    for (int t = 0; t < 8; t++) m[t] = -3.4e38f;
#pragma unroll
    for (int dh = 0; dh < 3; dh++) {
        int lr = hl + dh;
#pragma unroll
        for (int dw = -1; dw <= 1; dw++) {
            int ww = w + dw;
            if (ww < 0 || ww > 31) continue;
            const float* pp = &sb[(lr * 32 + ww) * 8];
#pragma unroll
            for (int t = 0; t < 8; t++) m[t] = fmaxf(m[t], pp[t]);
        }
    }
    float mx = m[0];
#pragma unroll
    for (int t = 1; t < 8; t++) mx = fmaxf(mx, m[t]);
    float e[8], ssum = 0.f;
#pragma unroll
    for (int t = 0; t < 8; t++) { e[t] = expf(m[t] - mx); ssum += e[t]; }
    float inv = 1.f / ssum;
    float* dst = &g_r[nt * 8192 + ((band * 8 + hl) * 32 + w) * 8];
    *(float4*)(dst + 0) = make_float4(e[0] * inv, e[1] * inv, e[2] * inv, e[3] * inv);
    *(float4*)(dst + 4) = make_float4(e[4] * inv, e[5] * inv, e[6] * inv, e[7] * inv);
}

// ---------------------------------------------------------------------------
// 6) Final routing iteration fused with transpose.
//    Block = 8 pixels of one (n,h) row; grid (4, 32, 8) = 1024 blocks, 256 thr.
// ---------------------------------------------------------------------------
__global__ __launch_bounds__(256) void route2t_kernel(float* __restrict__ out) {
    __shared__ float vt[8 * 516];
    const int wq = blockIdx.x;          // quarter-row
    const int h  = blockIdx.y;
    const int n  = blockIdx.z;
    const int tid = threadIdx.x;
    const int half = tid >> 7;
    const int t1 = (tid & 127) >> 4;
    const int z4 = tid & 15;
    const int w0 = wq * 8;

#pragma unroll
    for (int wp = 0; wp < 4; wp++) {
        const int wl = wp * 2 + half;
        const int w = w0 + wl;
        const int hw = h * 32 + w;
        const int pix = (n * 32 + h) * 32 + w;

        float r[8];
#pragma unroll
        for (int t0 = 0; t0 < 8; t0++)
            r[t0] = g_r[((n * 8 + t0) * 1024 + hw) * 8 + t1];

        float4 p = make_float4(0.f, 0.f, 0.f, 0.f);
        const float4* up = (const float4*)g_u2 + (size_t)pix * 1024 + t1 * 16 + z4;
#pragma unroll
        for (int t0 = 0; t0 < 8; t0++) {
            float4 u = up[t0 * 128];
            p.x += r[t0] * u.x; p.y += r[t0] * u.y;
            p.z += r[t0] * u.z; p.w += r[t0] * u.w;
        }
        float n2 = p.x * p.x + p.y * p.y + p.z * p.z + p.w * p.w;
#pragma unroll
        for (int mm = 1; mm < 16; mm <<= 1) n2 += __shfl_xor_sync(0xffffffffu, n2, mm);
        float s = n2 / (1.f + n2) * rsqrtf(n2 + 1e-9f);

        *(float4*)&vt[wl * 516 + t1 * 64 + z4 * 4] =
            make_float4(p.x * s, p.y * s, p.z * s, p.w * s);
    }
    __syncthreads();

    float* dst = out + (size_t)n * 512 * 1024 + h * 32 + w0;
#pragma unroll
    for (int k = 0; k < 8; k++) {
        int idx = tid + 256 * k;            // 0..2047 float2 slots
        int row = idx >> 2, col2 = idx & 3; // 512 rows x 4 float2-cols
        float2 v2 = make_float2(vt[(col2 * 2 + 0) * 516 + row],
                                vt[(col2 * 2 + 1) * 516 + row]);
        *(float2*)(dst + (size_t)row * 1024 + col2 * 2) = v2;
    }
}

// ---------------------------------------------------------------------------
extern "C" void kernel_launch(void* const* d_in, const int* in_sizes, int n_in,
                              void* d_out, int out_size) {
    const float* x    = (const float*)d_in[0];
    const float* W    = (const float*)d_in[1];
    const float* bias = (const float*)d_in[2];
    float* out = (float*)d_out;

    cudaFuncSetAttribute(conv_mma_kernel,
                         cudaFuncAttributeMaxDynamicSharedMemorySize, CONV_SMEM);

    xt_kernel<<<dim3(64, 64), 256>>>(x);
    w2_kernel<<<576, 256>>>(W);
    conv_mma_kernel<<<dim3(8, 4, 64), 256, CONV_SMEM>>>(bias);

    route_kernel<0><<<8192, 128>>>();
    pool_softmax_kernel<<<dim3(4, 64), 256>>>();
    route_kernel<1><<<8192, 128>>>();
    pool_softmax_kernel<<<dim3(4, 64), 256>>>();
    route2t_kernel<<<dim3(4, 32, 8), 256>>>(out);
}

// round 15
// speedup vs baseline: 1.8273x; 1.3209x over previous
#include <cuda_runtime.h>
#include <cuda_fp16.h>
#include <cstdint>

// CapsuleLayer: conv(stride2,3x3) via mma.sync fp16 (m16n8k16, fp32 accum),
// u_hat stored fp16, 3x dynamic routing (fp32 math), fused final route+transpose.
// x: [8,8,32,64,64] fp32   W: [512,32,3,3]   bias: [512]
// out: [8,8,64,32,32] (N,T1,Z1,H1,W1) fp32

#define DEVINL __device__ __forceinline__

DEVINL uint32_t smem_u32(const void* p) {
    uint32_t a;
    asm("{ .reg .u64 t; cvta.to.shared.u64 t, %1; cvt.u32.u64 %0, t; }" : "=r"(a) : "l"(p));
    return a;
}
DEVINL void cp16(uint32_t dst, const void* src) {
    asm volatile("cp.async.cg.shared.global [%0], [%1], 16;" ::"r"(dst), "l"(src) : "memory");
}
DEVINL uint32_t h2u(__half2 h) { return *reinterpret_cast<uint32_t*>(&h); }
DEVINL float2 u2f(uint32_t u) {
    __half2 h = *reinterpret_cast<__half2*>(&u);
    return __half22float2(h);
}

// ---------------------------------------------------------------------------
__device__ __align__(128) __half g_xh[64 * 66 * 66 * 32];        // NHWC padded, fp16
__device__ __align__(128) __half g_wh[9 * 512 * 32];             // [kpos][oc][ic], fp16
__device__ __align__(128) __half g_u2h[8 * 32 * 32 * 8 * 8 * 64];// [n][h][w][t0][t1][z] fp16
__device__ __align__(128) float g_b [8 * 8 * 32 * 32 * 8];       // [n][t0][h][w][t1]
__device__ __align__(128) float g_r [8 * 8 * 32 * 32 * 8];

// ---------------------------------------------------------------------------
// 1) x -> g_xh  (NCHW -> padded NHWC, fp16)
// ---------------------------------------------------------------------------
__global__ __launch_bounds__(256) void xt_kernel(const float* __restrict__ x) {
    __shared__ float s[64 * 33];
    const int b = blockIdx.y, h0 = blockIdx.x;
    const int t = threadIdx.x;
    const int lane = t & 31, icg = t >> 5;
    const float* xp = x + ((size_t)(b * 32) * 64 + h0) * 64;
#pragma unroll
    for (int i = 0; i < 4; i++) {
        int ic = icg + 8 * i;
        s[lane * 33 + ic]        = xp[(size_t)ic * 4096 + lane];
        s[(lane + 32) * 33 + ic] = xp[(size_t)ic * 4096 + lane + 32];
    }
    __syncthreads();
    __half2* dst = (__half2*)(g_xh + (((size_t)b * 66 + h0 + 1) * 66 + 1) * 32);
#pragma unroll
    for (int i = 0; i < 4; i++) {
        int idx = t + 256 * i;              // 1024 half2 = 64 px * 16 pairs
        int w0 = idx >> 4, icp = idx & 15;
        dst[w0 * 16 + icp] = __floats2half2_rn(s[w0 * 33 + 2 * icp],
                                               s[w0 * 33 + 2 * icp + 1]);
    }
}

// ---------------------------------------------------------------------------
// 2) W -> g_wh [kpos][oc][ic] fp16
// ---------------------------------------------------------------------------
__global__ void w2_kernel(const float* __restrict__ W) {
    int idx = blockIdx.x * 256 + threadIdx.x;   // oc*288 + ic*9 + kp
    if (idx >= 512 * 288) return;
    int oc = idx / 288, r = idx % 288, ic = r / 9, kp = r % 9;
    g_wh[((size_t)kp * 512 + oc) * 32 + ic] = __float2half_rn(W[idx]);
}

// ---------------------------------------------------------------------------
// 3) conv via mma.sync fp16 m16n8k16, fp16 u_hat output.
// ---------------------------------------------------------------------------
#define RSTRB 80                     // bytes per row in smem tile
#define RSTR32 20                    // u32 stride per row
#define TILE_B (128 * RSTRB)         // 10240 bytes per tile
#define CONV_SMEM 67584              // stage[128px][132] floats dominates

__global__ __launch_bounds__(256, 2) void conv_mma_kernel(const float* __restrict__ bias) {
    extern __shared__ float dsm[];
    const uint32_t sbase = smem_u32(dsm);
    const uint32_t offA[2] = {0u, 2u * TILE_B};
    const uint32_t offB[2] = {TILE_B, 3u * TILE_B};

    const int tid = threadIdx.x;
    const int wid = tid >> 5, lane = tid & 31;
    const int gid = lane >> 2, tig = lane & 3;

    const int pt = blockIdx.x;    // pixel tile (4 output rows)
    const int m  = blockIdx.y;    // oc block of 128
    const int b  = blockIdx.z;    // n*8 + t0
    const int h0 = pt * 4;

    const int m0 = (wid & 1) * 64;
    const int n0 = (wid >> 1) * 32;

    float acc[4][4][4];
#pragma unroll
    for (int mi = 0; mi < 4; mi++)
#pragma unroll
        for (int ni = 0; ni < 4; ni++)
#pragma unroll
            for (int j = 0; j < 4; j++) acc[mi][ni][j] = 0.f;

    auto issue = [&](int s, int buf) {
        const int kh = s / 3, kw = s % 3;
        const uint4* Asrc = (const uint4*)g_wh + ((size_t)s * 512 + m * 128) * 4;
        const int ihb = 2 * h0 + kh;
#pragma unroll
        for (int i = 0; i < 2; i++) {
            int c = tid + 256 * i;          // 0..511
            int o = c >> 2, q = c & 3;
            cp16(sbase + offA[buf] + o * RSTRB + q * 16, Asrc + c);
            int hl = o >> 5, wl = o & 31;
            const uint4* src =
                (const uint4*)g_xh + (((size_t)b * 66 + ihb + 2 * hl) * 66 + 2 * wl + kw) * 4 + q;
            cp16(sbase + offB[buf] + o * RSTRB + q * 16, src);
        }
        asm volatile("cp.async.commit_group;");
    };

    issue(0, 0);

    for (int s = 0; s < 9; s++) {
        if (s < 8) {
            issue(s + 1, (s + 1) & 1);
            asm volatile("cp.async.wait_group 1;" ::: "memory");
        } else {
            asm volatile("cp.async.wait_group 0;" ::: "memory");
        }
        __syncthreads();

        const uint32_t* sA = (const uint32_t*)dsm + offA[s & 1] / 4;
        const uint32_t* sB = (const uint32_t*)dsm + offB[s & 1] / 4;

#pragma unroll
        for (int kk = 0; kk < 2; kk++) {    // two 16-ic chunks per stage
            const int kc = kk * 8 + tig;
            uint32_t a[4][4];
#pragma unroll
            for (int mi = 0; mi < 4; mi++) {
                int r = m0 + mi * 16 + gid;
                a[mi][0] = sA[r * RSTR32 + kc];
                a[mi][1] = sA[(r + 8) * RSTR32 + kc];
                a[mi][2] = sA[r * RSTR32 + kc + 4];
                a[mi][3] = sA[(r + 8) * RSTR32 + kc + 4];
            }
            uint32_t bf[4][2];
#pragma unroll
            for (int ni = 0; ni < 4; ni++) {
                int cn = n0 + ni * 8 + gid;
                bf[ni][0] = sB[cn * RSTR32 + kc];
                bf[ni][1] = sB[cn * RSTR32 + kc + 4];
            }
#pragma unroll
            for (int mi = 0; mi < 4; mi++)
#pragma unroll
                for (int ni = 0; ni < 4; ni++)
                    asm volatile(
                        "mma.sync.aligned.m16n8k16.row.col.f32.f16.f16.f32 "
                        "{%0,%1,%2,%3}, {%4,%5,%6,%7}, {%8,%9}, {%0,%1,%2,%3};"
                        : "+f"(acc[mi][ni][0]), "+f"(acc[mi][ni][1]),
                          "+f"(acc[mi][ni][2]), "+f"(acc[mi][ni][3])
                        : "r"(a[mi][0]), "r"(a[mi][1]), "r"(a[mi][2]), "r"(a[mi][3]),
                          "r"(bf[ni][0]), "r"(bf[ni][1]));
        }
        __syncthreads();
    }

    // Epilogue: regs -> stage[px][oc] (+bias) -> g_u2h (fp16)
    float* stage = dsm;
#pragma unroll
    for (int mi = 0; mi < 4; mi++) {
        int r = m0 + mi * 16 + gid;
        float bi0 = bias[m * 128 + r];
        float bi1 = bias[m * 128 + r + 8];
#pragma unroll
        for (int ni = 0; ni < 4; ni++) {
            int cn = n0 + ni * 8 + 2 * tig;
            stage[cn * 132 + r]           = acc[mi][ni][0] + bi0;
            stage[(cn + 1) * 132 + r]     = acc[mi][ni][1] + bi0;
            stage[cn * 132 + r + 8]       = acc[mi][ni][2] + bi1;
            stage[(cn + 1) * 132 + r + 8] = acc[mi][ni][3] + bi1;
        }
    }
    __syncthreads();

    const int n = b >> 3, t0 = b & 7;
#pragma unroll
    for (int k = 0; k < 8; k++) {
        int idx = tid + 256 * k;            // 2048 chunks of 8 oc
        int p = idx >> 4, q = idx & 15;
        int h = h0 + (p >> 5), w = p & 31;
        float4 v0 = *(const float4*)(stage + p * 132 + q * 8);
        float4 v1 = *(const float4*)(stage + p * 132 + q * 8 + 4);
        uint4 pk;
        pk.x = h2u(__floats2half2_rn(v0.x, v0.y));
        pk.y = h2u(__floats2half2_rn(v0.z, v0.w));
        pk.z = h2u(__floats2half2_rn(v1.x, v1.y));
        pk.w = h2u(__floats2half2_rn(v1.z, v1.w));
        size_t off = ((((size_t)(n * 32 + h) * 32 + w) * 8 + t0) * 512) + m * 128 + q * 8;
        *(uint4*)(g_u2h + off) = pk;
    }
}

// ---------------------------------------------------------------------------
// 4) Routing iterations 0/1: 2 pixels per block, 64 threads each.
//    Thread owns (t1, 8 z-values as one uint4 of halves).
// ---------------------------------------------------------------------------
template <int MODE>
__global__ __launch_bounds__(128) void route_kernel() {
    __shared__ float sr[128];           // [ph][t0*8+t1]

    const int tid = threadIdx.x;
    const int ph = tid >> 6;
    const int pix = blockIdx.x * 2 + ph;
    const int n = pix >> 10;
    const int hw = pix & 1023;
    const int lt = tid & 63;
    const int t1 = lt >> 3;
    const int z8 = lt & 7;

    if (MODE >= 1) {
        int rt0 = lt >> 3, rt1 = lt & 7;
        sr[ph * 64 + rt0 * 8 + rt1] = g_r[((n * 8 + rt0) * 1024 + hw) * 8 + rt1];
    }

    uint4 uu[8];
    const uint4* up = (const uint4*)g_u2h + (size_t)pix * 512 + t1 * 8 + z8;
#pragma unroll
    for (int t0 = 0; t0 < 8; t0++) uu[t0] = up[t0 * 64];

    if (MODE >= 1) __syncthreads();

    float p[8];
#pragma unroll
    for (int j = 0; j < 8; j++) p[j] = 0.f;
#pragma unroll
    for (int t0 = 0; t0 < 8; t0++) {
        float r = (MODE == 0) ? 0.125f : sr[ph * 64 + t0 * 8 + t1];
        float2 f0 = u2f(uu[t0].x), f1 = u2f(uu[t0].y);
        float2 f2 = u2f(uu[t0].z), f3 = u2f(uu[t0].w);
        p[0] += r * f0.x; p[1] += r * f0.y; p[2] += r * f1.x; p[3] += r * f1.y;
        p[4] += r * f2.x; p[5] += r * f2.y; p[6] += r * f3.x; p[7] += r * f3.y;
    }
    float n2 = 0.f;
#pragma unroll
    for (int j = 0; j < 8; j++) n2 += p[j] * p[j];
#pragma unroll
    for (int mm = 1; mm < 8; mm <<= 1) n2 += __shfl_xor_sync(0xffffffffu, n2, mm);
    float s = n2 / (1.f + n2) * rsqrtf(n2 + 1e-9f);
    float v[8];
#pragma unroll
    for (int j = 0; j < 8; j++) v[j] = p[j] * s;

    float d[8];
#pragma unroll
    for (int t0 = 0; t0 < 8; t0++) {
        float2 f0 = u2f(uu[t0].x), f1 = u2f(uu[t0].y);
        float2 f2 = u2f(uu[t0].z), f3 = u2f(uu[t0].w);
        d[t0] = f0.x * v[0] + f0.y * v[1] + f1.x * v[2] + f1.y * v[3] +
                f2.x * v[4] + f2.y * v[5] + f3.x * v[6] + f3.y * v[7];
    }
#pragma unroll
    for (int mm = 1; mm < 8; mm <<= 1) {
#pragma unroll
        for (int t0 = 0; t0 < 8; t0++)
            d[t0] += __shfl_xor_sync(0xffffffffu, d[t0], mm);
    }
    if (z8 == 0) {
#pragma unroll
        for (int t0 = 0; t0 < 8; t0++) {
            float* bp = &g_b[((n * 8 + t0) * 1024 + hw) * 8 + t1];
            if (MODE == 0) *bp = d[t0];
            else           *bp += d[t0];
        }
    }
}

// ---------------------------------------------------------------------------
// 5) r = softmax_t1(maxpool3x3(b)).  grid (band=4, nt=64), 256 thr, h-banded.
// ---------------------------------------------------------------------------
__global__ __launch_bounds__(256) void pool_softmax_kernel() {
    __shared__ float sb[10 * 32 * 8];
    const int band = blockIdx.x, nt = blockIdx.y;
    const int tid = threadIdx.x;
    const int h_base = band * 8 - 1;

    for (int i = tid; i < 640; i += 256) {
        int lr = i >> 6, rem = i & 63;
        int gh = h_base + lr;
        float4 v;
        if (gh >= 0 && gh < 32)
            v = ((const float4*)(g_b + nt * 8192 + gh * 256))[rem];
        else
            v = make_float4(-3.4e38f, -3.4e38f, -3.4e38f, -3.4e38f);
        ((float4*)sb)[i] = v;
    }
    __syncthreads();

    const int hl = tid >> 5, w = tid & 31;
    float m[8];
#pragma unroll
    for (int t = 0; t < 8; t++) m[t] = -3.4e38f;
#pragma unroll
    for (int dh = 0; dh < 3; dh++) {
        int lr = hl + dh;
#pragma unroll
        for (int dw = -1; dw <= 1; dw++) {
            int ww = w + dw;
            if (ww < 0 || ww > 31) continue;
            const float* pp = &sb[(lr * 32 + ww) * 8];
#pragma unroll
            for (int t = 0; t < 8; t++) m[t] = fmaxf(m[t], pp[t]);
        }
    }
    float mx = m[0];
#pragma unroll
    for (int t = 1; t < 8; t++) mx = fmaxf(mx, m[t]);
    float e[8], ssum = 0.f;
#pragma unroll
    for (int t = 0; t < 8; t++) { e[t] = expf(m[t] - mx); ssum += e[t]; }
    float inv = 1.f / ssum;
    float* dst = &g_r[nt * 8192 + ((band * 8 + hl) * 32 + w) * 8];
    *(float4*)(dst + 0) = make_float4(e[0] * inv, e[1] * inv, e[2] * inv, e[3] * inv);
    *(float4*)(dst + 4) = make_float4(e[4] * inv, e[5] * inv, e[6] * inv, e[7] * inv);
}

// ---------------------------------------------------------------------------
// 6) Final routing iteration fused with transpose.
//    Block = 8 pixels of one (n,h) row; 256 thr = 4 pixel-slots x 64, 2 iters.
// ---------------------------------------------------------------------------
__global__ __launch_bounds__(256) void route2t_kernel(float* __restrict__ out) {
    __shared__ float vt[8 * 516];
    const int wq = blockIdx.x;          // quarter-row
    const int h  = blockIdx.y;
    const int n  = blockIdx.z;
    const int tid = threadIdx.x;
    const int slot = tid >> 6;          // 0..3
    const int lt = tid & 63;
    const int t1 = lt >> 3;
    const int z8 = lt & 7;
    const int w0 = wq * 8;

#pragma unroll
    for (int wp = 0; wp < 2; wp++) {
        const int wl = wp * 4 + slot;   // 0..7
        const int w = w0 + wl;
        const int hw = h * 32 + w;
        const int pix = (n * 32 + h) * 32 + w;

        float r[8];
#pragma unroll
        for (int t0 = 0; t0 < 8; t0++)
            r[t0] = g_r[((n * 8 + t0) * 1024 + hw) * 8 + t1];

        float p[8];
#pragma unroll
        for (int j = 0; j < 8; j++) p[j] = 0.f;
        const uint4* up = (const uint4*)g_u2h + (size_t)pix * 512 + t1 * 8 + z8;
#pragma unroll
        for (int t0 = 0; t0 < 8; t0++) {
            uint4 uu = up[t0 * 64];
            float2 f0 = u2f(uu.x), f1 = u2f(uu.y), f2 = u2f(uu.z), f3 = u2f(uu.w);
            p[0] += r[t0] * f0.x; p[1] += r[t0] * f0.y;
            p[2] += r[t0] * f1.x; p[3] += r[t0] * f1.y;
            p[4] += r[t0] * f2.x; p[5] += r[t0] * f2.y;
            p[6] += r[t0] * f3.x; p[7] += r[t0] * f3.y;
        }
        float n2 = 0.f;
#pragma unroll
        for (int j = 0; j < 8; j++) n2 += p[j] * p[j];
#pragma unroll
        for (int mm = 1; mm < 8; mm <<= 1) n2 += __shfl_xor_sync(0xffffffffu, n2, mm);
        float s = n2 / (1.f + n2) * rsqrtf(n2 + 1e-9f);

        float* vp = &vt[wl * 516 + t1 * 64 + z8 * 8];
        *(float4*)(vp + 0) = make_float4(p[0] * s, p[1] * s, p[2] * s, p[3] * s);
        *(float4*)(vp + 4) = make_float4(p[4] * s, p[5] * s, p[6] * s, p[7] * s);
    }
    __syncthreads();

    float* dst = out + (size_t)n * 512 * 1024 + h * 32 + w0;
#pragma unroll
    for (int k = 0; k < 8; k++) {
        int idx = tid + 256 * k;            // 0..2047 float2 slots
        int row = idx >> 2, col2 = idx & 3; // 512 rows x 4 float2-cols
        float2 v2 = make_float2(vt[(col2 * 2 + 0) * 516 + row],
                                vt[(col2 * 2 + 1) * 516 + row]);
        *(float2*)(dst + (size_t)row * 1024 + col2 * 2) = v2;
    }
}

// ---------------------------------------------------------------------------
extern "C" void kernel_launch(void* const* d_in, const int* in_sizes, int n_in,
                              void* d_out, int out_size) {
    const float* x    = (const float*)d_in[0];
    const float* W    = (const float*)d_in[1];
    const float* bias = (const float*)d_in[2];
    float* out = (float*)d_out;

    cudaFuncSetAttribute(conv_mma_kernel,
                         cudaFuncAttributeMaxDynamicSharedMemorySize, CONV_SMEM);

    xt_kernel<<<dim3(64, 64), 256>>>(x);
    w2_kernel<<<576, 256>>>(W);
    conv_mma_kernel<<<dim3(8, 4, 64), 256, CONV_SMEM>>>(bias);

    route_kernel<0><<<4096, 128>>>();
    pool_softmax_kernel<<<dim3(4, 64), 256>>>();
    route_kernel<1><<<4096, 128>>>();
    pool_softmax_kernel<<<dim3(4, 64), 256>>>();
    route2t_kernel<<<dim3(4, 32, 8), 256>>>(out);
}

// round 16
// speedup vs baseline: 2.0418x; 1.1174x over previous
#include <cuda_runtime.h>
#include <cuda_fp16.h>
#include <cstdint>

// CapsuleLayer: conv(stride2,3x3) via mma.sync fp16 (m16n8k16, fp32 accum,
// ldmatrix fragment loads), u_hat stored fp16, 3x dynamic routing (fp32 math),
// fused final route+transpose.
// x: [8,8,32,64,64] fp32   W: [512,32,3,3]   bias: [512]
// out: [8,8,64,32,32] (N,T1,Z1,H1,W1) fp32

#define DEVINL __device__ __forceinline__

DEVINL uint32_t smem_u32(const void* p) {
    uint32_t a;
    asm("{ .reg .u64 t; cvta.to.shared.u64 t, %1; cvt.u32.u64 %0, t; }" : "=r"(a) : "l"(p));
    return a;
}
DEVINL void cp16(uint32_t dst, const void* src) {
    asm volatile("cp.async.cg.shared.global [%0], [%1], 16;" ::"r"(dst), "l"(src) : "memory");
}
DEVINL uint32_t h2u(__half2 h) { return *reinterpret_cast<uint32_t*>(&h); }
DEVINL float2 u2f(uint32_t u) {
    __half2 h = *reinterpret_cast<__half2*>(&u);
    return __half22float2(h);
}
DEVINL void ldmx4(uint32_t& r0, uint32_t& r1, uint32_t& r2, uint32_t& r3, uint32_t addr) {
    asm volatile("ldmatrix.sync.aligned.m8n8.x4.shared.b16 {%0,%1,%2,%3}, [%4];"
                 : "=r"(r0), "=r"(r1), "=r"(r2), "=r"(r3) : "r"(addr));
}
DEVINL void ldmx2(uint32_t& r0, uint32_t& r1, uint32_t addr) {
    asm volatile("ldmatrix.sync.aligned.m8n8.x2.shared.b16 {%0,%1}, [%2];"
                 : "=r"(r0), "=r"(r1) : "r"(addr));
}

// ---------------------------------------------------------------------------
__device__ __align__(128) __half g_xh[64 * 66 * 66 * 32];        // NHWC padded, fp16
__device__ __align__(128) __half g_wh[9 * 512 * 32];             // [kpos][oc][ic], fp16
__device__ __align__(128) __half g_u2h[8 * 32 * 32 * 8 * 8 * 64];// [n][h][w][t0][t1][z] fp16
__device__ __align__(128) float g_b [8 * 8 * 32 * 32 * 8];       // [n][t0][h][w][t1]
__device__ __align__(128) float g_r [8 * 8 * 32 * 32 * 8];

// ---------------------------------------------------------------------------
// 1) x -> g_xh  (NCHW -> padded NHWC, fp16)
// ---------------------------------------------------------------------------
__global__ __launch_bounds__(256) void xt_kernel(const float* __restrict__ x) {
    __shared__ float s[64 * 33];
    const int b = blockIdx.y, h0 = blockIdx.x;
    const int t = threadIdx.x;
    const int lane = t & 31, icg = t >> 5;
    const float* xp = x + ((size_t)(b * 32) * 64 + h0) * 64;
#pragma unroll
    for (int i = 0; i < 4; i++) {
        int ic = icg + 8 * i;
        s[lane * 33 + ic]        = xp[(size_t)ic * 4096 + lane];
        s[(lane + 32) * 33 + ic] = xp[(size_t)ic * 4096 + lane + 32];
    }
    __syncthreads();
    __half2* dst = (__half2*)(g_xh + (((size_t)b * 66 + h0 + 1) * 66 + 1) * 32);
#pragma unroll
    for (int i = 0; i < 4; i++) {
        int idx = t + 256 * i;              // 1024 half2 = 64 px * 16 pairs
        int w0 = idx >> 4, icp = idx & 15;
        dst[w0 * 16 + icp] = __floats2half2_rn(s[w0 * 33 + 2 * icp],
                                               s[w0 * 33 + 2 * icp + 1]);
    }
}

// ---------------------------------------------------------------------------
// 2) W -> g_wh [kpos][oc][ic] fp16
// ---------------------------------------------------------------------------
__global__ void w2_kernel(const float* __restrict__ W) {
    int idx = blockIdx.x * 256 + threadIdx.x;   // oc*288 + ic*9 + kp
    if (idx >= 512 * 288) return;
    int oc = idx / 288, r = idx % 288, ic = r / 9, kp = r % 9;
    g_wh[((size_t)kp * 512 + oc) * 32 + ic] = __float2half_rn(W[idx]);
}

// ---------------------------------------------------------------------------
// 3) conv via mma.sync fp16 m16n8k16, ldmatrix fragment loads, fp16 u_hat out.
// ---------------------------------------------------------------------------
#define RSTRB 80                     // bytes per row in smem tile
#define TILE_B (128 * RSTRB)         // 10240 bytes per tile
#define CONV_SMEM 67584              // stage[128px][132] floats dominates

__global__ __launch_bounds__(256, 2) void conv_mma_kernel(const float* __restrict__ bias) {
    extern __shared__ float dsm[];
    const uint32_t sbase = smem_u32(dsm);
    const uint32_t offA[2] = {0u, 2u * TILE_B};
    const uint32_t offB[2] = {TILE_B, 3u * TILE_B};

    const int tid = threadIdx.x;
    const int wid = tid >> 5, lane = tid & 31;
    const int gid = lane >> 2, tig = lane & 3;

    const int pt = blockIdx.x;    // pixel tile (4 output rows)
    const int m  = blockIdx.y;    // oc block of 128
    const int b  = blockIdx.z;    // n*8 + t0
    const int h0 = pt * 4;

    const int m0 = (wid & 1) * 64;
    const int n0 = (wid >> 1) * 32;

    // ldmatrix lane-address offsets (bytes within tile)
    uint32_t aoff[4], boff[4];
#pragma unroll
    for (int mi = 0; mi < 4; mi++)
        aoff[mi] = (uint32_t)((m0 + mi * 16 + (lane & 15)) * RSTRB + (lane >> 4) * 16);
#pragma unroll
    for (int ni = 0; ni < 4; ni++)
        boff[ni] = (uint32_t)((n0 + ni * 8 + (lane & 7)) * RSTRB + ((lane >> 3) & 1) * 16);

    float acc[4][4][4];
#pragma unroll
    for (int mi = 0; mi < 4; mi++)
#pragma unroll
        for (int ni = 0; ni < 4; ni++)
#pragma unroll
            for (int j = 0; j < 4; j++) acc[mi][ni][j] = 0.f;

    auto issue = [&](int s, int buf) {
        const int kh = s / 3, kw = s % 3;
        const uint4* Asrc = (const uint4*)g_wh + ((size_t)s * 512 + m * 128) * 4;
        const int ihb = 2 * h0 + kh;
#pragma unroll
        for (int i = 0; i < 2; i++) {
            int c = tid + 256 * i;          // 0..511
            int o = c >> 2, q = c & 3;
            cp16(sbase + offA[buf] + o * RSTRB + q * 16, Asrc + c);
            int hl = o >> 5, wl = o & 31;
            const uint4* src =
                (const uint4*)g_xh + (((size_t)b * 66 + ihb + 2 * hl) * 66 + 2 * wl + kw) * 4 + q;
            cp16(sbase + offB[buf] + o * RSTRB + q * 16, src);
        }
        asm volatile("cp.async.commit_group;");
    };

    issue(0, 0);

    for (int s = 0; s < 9; s++) {
        if (s < 8) {
            issue(s + 1, (s + 1) & 1);
            asm volatile("cp.async.wait_group 1;" ::: "memory");
        } else {
            asm volatile("cp.async.wait_group 0;" ::: "memory");
        }
        __syncthreads();

        const uint32_t aA = sbase + offA[s & 1];
        const uint32_t aB = sbase + offB[s & 1];

#pragma unroll
        for (int kk = 0; kk < 2; kk++) {    // two 16-ic chunks per stage
            const uint32_t ko = kk * 32;    // 16 halves
            uint32_t a[4][4];
#pragma unroll
            for (int mi = 0; mi < 4; mi++)
                ldmx4(a[mi][0], a[mi][1], a[mi][2], a[mi][3], aA + aoff[mi] + ko);
            uint32_t bf[4][2];
#pragma unroll
            for (int ni = 0; ni < 4; ni++)
                ldmx2(bf[ni][0], bf[ni][1], aB + boff[ni] + ko);
#pragma unroll
            for (int mi = 0; mi < 4; mi++)
#pragma unroll
                for (int ni = 0; ni < 4; ni++)
                    asm volatile(
                        "mma.sync.aligned.m16n8k16.row.col.f32.f16.f16.f32 "
                        "{%0,%1,%2,%3}, {%4,%5,%6,%7}, {%8,%9}, {%0,%1,%2,%3};"
                        : "+f"(acc[mi][ni][0]), "+f"(acc[mi][ni][1]),
                          "+f"(acc[mi][ni][2]), "+f"(acc[mi][ni][3])
                        : "r"(a[mi][0]), "r"(a[mi][1]), "r"(a[mi][2]), "r"(a[mi][3]),
                          "r"(bf[ni][0]), "r"(bf[ni][1]));
        }
        __syncthreads();
    }

    // Epilogue: regs -> stage[px][oc] (+bias) -> g_u2h (fp16)
    float* stage = dsm;
#pragma unroll
    for (int mi = 0; mi < 4; mi++) {
        int r = m0 + mi * 16 + gid;
        float bi0 = bias[m * 128 + r];
        float bi1 = bias[m * 128 + r + 8];
#pragma unroll
        for (int ni = 0; ni < 4; ni++) {
            int cn = n0 + ni * 8 + 2 * tig;
            stage[cn * 132 + r]           = acc[mi][ni][0] + bi0;
            stage[(cn + 1) * 132 + r]     = acc[mi][ni][1] + bi0;
            stage[cn * 132 + r + 8]       = acc[mi][ni][2] + bi1;
            stage[(cn + 1) * 132 + r + 8] = acc[mi][ni][3] + bi1;
        }
    }
    __syncthreads();

    const int n = b >> 3, t0 = b & 7;
#pragma unroll
    for (int k = 0; k < 8; k++) {
        int idx = tid + 256 * k;            // 2048 chunks of 8 oc
        int p = idx >> 4, q = idx & 15;
        int h = h0 + (p >> 5), w = p & 31;
        float4 v0 = *(const float4*)(stage + p * 132 + q * 8);
        float4 v1 = *(const float4*)(stage + p * 132 + q * 8 + 4);
        uint4 pk;
        pk.x = h2u(__floats2half2_rn(v0.x, v0.y));
        pk.y = h2u(__floats2half2_rn(v0.z, v0.w));
        pk.z = h2u(__floats2half2_rn(v1.x, v1.y));
        pk.w = h2u(__floats2half2_rn(v1.z, v1.w));
        size_t off = ((((size_t)(n * 32 + h) * 32 + w) * 8 + t0) * 512) + m * 128 + q * 8;
        *(uint4*)(g_u2h + off) = pk;
    }
}

// ---------------------------------------------------------------------------
// 4) Routing iterations 0/1: 2 pixels per block, 64 threads each.
// ---------------------------------------------------------------------------
template <int MODE>
__global__ __launch_bounds__(128) void route_kernel() {
    __shared__ float sr[128];           // [ph][t0*8+t1]

    const int tid = threadIdx.x;
    const int ph = tid >> 6;
    const int pix = blockIdx.x * 2 + ph;
    const int n = pix >> 10;
    const int hw = pix & 1023;
    const int lt = tid & 63;
    const int t1 = lt >> 3;
    const int z8 = lt & 7;

    if (MODE >= 1) {
        int rt0 = lt >> 3, rt1 = lt & 7;
        sr[ph * 64 + rt0 * 8 + rt1] = g_r[((n * 8 + rt0) * 1024 + hw) * 8 + rt1];
    }

    uint4 uu[8];
    const uint4* up = (const uint4*)g_u2h + (size_t)pix * 512 + t1 * 8 + z8;
#pragma unroll
    for (int t0 = 0; t0 < 8; t0++) uu[t0] = up[t0 * 64];

    if (MODE >= 1) __syncthreads();

    float p[8];
#pragma unroll
    for (int j = 0; j < 8; j++) p[j] = 0.f;
#pragma unroll
    for (int t0 = 0; t0 < 8; t0++) {
        float r = (MODE == 0) ? 0.125f : sr[ph * 64 + t0 * 8 + t1];
        float2 f0 = u2f(uu[t0].x), f1 = u2f(uu[t0].y);
        float2 f2 = u2f(uu[t0].z), f3 = u2f(uu[t0].w);
        p[0] += r * f0.x; p[1] += r * f0.y; p[2] += r * f1.x; p[3] += r * f1.y;
        p[4] += r * f2.x; p[5] += r * f2.y; p[6] += r * f3.x; p[7] += r * f3.y;
    }
    float n2 = 0.f;
#pragma unroll
    for (int j = 0; j < 8; j++) n2 += p[j] * p[j];
#pragma unroll
    for (int mm = 1; mm < 8; mm <<= 1) n2 += __shfl_xor_sync(0xffffffffu, n2, mm);
    float s = n2 / (1.f + n2) * rsqrtf(n2 + 1e-9f);
    float v[8];
#pragma unroll
    for (int j = 0; j < 8; j++) v[j] = p[j] * s;

    float d[8];
#pragma unroll
    for (int t0 = 0; t0 < 8; t0++) {
        float2 f0 = u2f(uu[t0].x), f1 = u2f(uu[t0].y);
        float2 f2 = u2f(uu[t0].z), f3 = u2f(uu[t0].w);
        d[t0] = f0.x * v[0] + f0.y * v[1] + f1.x * v[2] + f1.y * v[3] +
                f2.x * v[4] + f2.y * v[5] + f3.x * v[6] + f3.y * v[7];
    }
#pragma unroll
    for (int mm = 1; mm < 8; mm <<= 1) {
#pragma unroll
        for (int t0 = 0; t0 < 8; t0++)
            d[t0] += __shfl_xor_sync(0xffffffffu, d[t0], mm);
    }
    if (z8 == 0) {
#pragma unroll
        for (int t0 = 0; t0 < 8; t0++) {
            float* bp = &g_b[((n * 8 + t0) * 1024 + hw) * 8 + t1];
            if (MODE == 0) *bp = d[t0];
            else           *bp += d[t0];
        }
    }
}

// ---------------------------------------------------------------------------
// 5) r = softmax_t1(maxpool3x3(b)).  grid (band=4, nt=64), 256 thr, h-banded.
// ---------------------------------------------------------------------------
__global__ __launch_bounds__(256) void pool_softmax_kernel() {
    __shared__ float sb[10 * 32 * 8];
    const int band = blockIdx.x, nt = blockIdx.y;
    const int tid = threadIdx.x;
    const int h_base = band * 8 - 1;

    for (int i = tid; i < 640; i += 256) {
        int lr = i >> 6, rem = i & 63;
        int gh = h_base + lr;
        float4 v;
        if (gh >= 0 && gh < 32)
            v = ((const float4*)(g_b + nt * 8192 + gh * 256))[rem];
        else
            v = make_float4(-3.4e38f, -3.4e38f, -3.4e38f, -3.4e38f);
        ((float4*)sb)[i] = v;
    }
    __syncthreads();

    const int hl = tid >> 5, w = tid & 31;
    float m[8];
#pragma unroll
    for (int t = 0; t < 8; t++) m[t] = -3.4e38f;
#pragma unroll
    for (int dh = 0; dh < 3; dh++) {
        int lr = hl + dh;
#pragma unroll
        for (int dw = -1; dw <= 1; dw++) {
            int ww = w + dw;
            if (ww < 0 || ww > 31) continue;
            const float* pp = &sb[(lr * 32 + ww) * 8];
#pragma unroll
            for (int t = 0; t < 8; t++) m[t] = fmaxf(m[t], pp[t]);
        }
    }
    float mx = m[0];
#pragma unroll
    for (int t = 1; t < 8; t++) mx = fmaxf(mx, m[t]);
    float e[8], ssum = 0.f;
#pragma unroll
    for (int t = 0; t < 8; t++) { e[t] = expf(m[t] - mx); ssum += e[t]; }
    float inv = 1.f / ssum;
    float* dst = &g_r[nt * 8192 + ((band * 8 + hl) * 32 + w) * 8];
    *(float4*)(dst + 0) = make_float4(e[0] * inv, e[1] * inv, e[2] * inv, e[3] * inv);
    *(float4*)(dst + 4) = make_float4(e[4] * inv, e[5] * inv, e[6] * inv, e[7] * inv);
}

// ---------------------------------------------------------------------------
// 6) Final routing iteration fused with transpose.
//    Block = 8 pixels of one (n,h) row; 256 thr = 4 pixel-slots x 64, 2 iters.
// ---------------------------------------------------------------------------
__global__ __launch_bounds__(256) void route2t_kernel(float* __restrict__ out) {
    __shared__ float vt[8 * 516];
    const int wq = blockIdx.x;          // quarter-row
    const int h  = blockIdx.y;
    const int n  = blockIdx.z;
    const int tid = threadIdx.x;
    const int slot = tid >> 6;          // 0..3
    const int lt = tid & 63;
    const int t1 = lt >> 3;
    const int z8 = lt & 7;
    const int w0 = wq * 8;

#pragma unroll
    for (int wp = 0; wp < 2; wp++) {
        const int wl = wp * 4 + slot;   // 0..7
        const int w = w0 + wl;
        const int hw = h * 32 + w;
        const int pix = (n * 32 + h) * 32 + w;

        float r[8];
#pragma unroll
        for (int t0 = 0; t0 < 8; t0++)
            r[t0] = g_r[((n * 8 + t0) * 1024 + hw) * 8 + t1];

        float p[8];
#pragma unroll
        for (int j = 0; j < 8; j++) p[j] = 0.f;
        const uint4* up = (const uint4*)g_u2h + (size_t)pix * 512 + t1 * 8 + z8;
#pragma unroll
        for (int t0 = 0; t0 < 8; t0++) {
            uint4 uu = up[t0 * 64];
            float2 f0 = u2f(uu.x), f1 = u2f(uu.y), f2 = u2f(uu.z), f3 = u2f(uu.w);
            p[0] += r[t0] * f0.x; p[1] += r[t0] * f0.y;
            p[2] += r[t0] * f1.x; p[3] += r[t0] * f1.y;
            p[4] += r[t0] * f2.x; p[5] += r[t0] * f2.y;
            p[6] += r[t0] * f3.x; p[7] += r[t0] * f3.y;
        }
        float n2 = 0.f;
#pragma unroll
        for (int j = 0; j < 8; j++) n2 += p[j] * p[j];
#pragma unroll
        for (int mm = 1; mm < 8; mm <<= 1) n2 += __shfl_xor_sync(0xffffffffu, n2, mm);
        float s = n2 / (1.f + n2) * rsqrtf(n2 + 1e-9f);

        float* vp = &vt[wl * 516 + t1 * 64 + z8 * 8];
        *(float4*)(vp + 0) = make_float4(p[0] * s, p[1] * s, p[2] * s, p[3] * s);
        *(float4*)(vp + 4) = make_float4(p[4] * s, p[5] * s, p[6] * s, p[7] * s);
    }
    __syncthreads();

    float* dst = out + (size_t)n * 512 * 1024 + h * 32 + w0;
#pragma unroll
    for (int k = 0; k < 8; k++) {
        int idx = tid + 256 * k;            // 0..2047 float2 slots
        int row = idx >> 2, col2 = idx & 3; // 512 rows x 4 float2-cols
        float2 v2 = make_float2(vt[(col2 * 2 + 0) * 516 + row],
                                vt[(col2 * 2 + 1) * 516 + row]);
        *(float2*)(dst + (size_t)row * 1024 + col2 * 2) = v2;
    }
}

// ---------------------------------------------------------------------------
extern "C" void kernel_launch(void* const* d_in, const int* in_sizes, int n_in,
                              void* d_out, int out_size) {
    const float* x    = (const float*)d_in[0];
    const float* W    = (const float*)d_in[1];
    const float* bias = (const float*)d_in[2];
    float* out = (float*)d_out;

    cudaFuncSetAttribute(conv_mma_kernel,
                         cudaFuncAttributeMaxDynamicSharedMemorySize, CONV_SMEM);

    xt_kernel<<<dim3(64, 64), 256>>>(x);
    w2_kernel<<<576, 256>>>(W);
    conv_mma_kernel<<<dim3(8, 4, 64), 256, CONV_SMEM>>>(bias);

    route_kernel<0><<<4096, 128>>>();
    pool_softmax_kernel<<<dim3(4, 64), 256>>>();
    route_kernel<1><<<4096, 128>>>();
    pool_softmax_kernel<<<dim3(4, 64), 256>>>();
    route2t_kernel<<<dim3(4, 32, 8), 256>>>(out);
}